// round 2
// baseline (speedup 1.0000x reference)
#include <cuda_runtime.h>
#include <math.h>

// ---------------- problem constants (structure is deterministic) ----------------
#define T_TREES   150
#define NPT       341          // nodes per tree (level-order, node0 = root)
#define NN        (T_TREES*NPT)
#define HID       256
#define IOUW      768
#define VOCAB     10000
#define LEAF_LOC0 85           // leaves are local nodes [85, 341)
#define LPT       256          // leaves per tree
#define NLEAF     (T_TREES*LPT)

// ---------------- scratch (device globals; no allocation allowed) ----------------
__device__ float g_P   [2u*VOCAB*IOUW];   // emb @ W_iou tables
__device__ float g_iou [2u*NLEAF*IOUW];   // iou scratch (max = leaves)
__device__ float g_h   [2u*NN*HID];
__device__ float g_c   [2u*NN*HID];
__device__ float g_cc  [2u*NLEAF*HID];    // f * c_child per edge (compact child order)
__device__ float g_ht  [2u*T_TREES*64*HID]; // h_tild (max parents/level = 64/tree)
__device__ float g_cs  [2u*T_TREES*64*HID]; // c_sum

__device__ __forceinline__ float sigf(float x) { return 1.0f/(1.0f+__expf(-x)); }

// ---------------- generic fp32 GEMM, K=256, C = A@B (+epilogue) ----------------
// A rows optionally mapped into the node array: ridx = (r/rpt)*NPT + start + r%rpt
struct GemmArgs {
    const float* A; const float* B; const float* bias; const float* Cst;
    float* Out; int M; int N; int start; int rpt; int use_map;
};

template<int EPI>   // 0: Out[r*N+col] = acc ; 1: fgate: Out[r*256+col] = sig(acc+bias)*Cst[ridx]
__global__ void gemm_k(GemmArgs a0, GemmArgs a1) {
    GemmArgs a = (blockIdx.z == 0) ? a0 : a1;
    const int BM = 64, BN = 64, BK = 16;
    __shared__ float As[BK][BM];   // stored transposed
    __shared__ float Bs[BK][BN];
    int tid = threadIdx.x;
    int tx = tid & 15, ty = tid >> 4;
    int m0 = blockIdx.y * BM, n0 = blockIdx.x * BN;
    float acc[4][4] = {};

    int arow = tid >> 2, acol = (tid & 3) * 4;      // A tile loader: one float4/thread
    const float* Aptr = nullptr;
    {
        int gr = m0 + arow;
        if (gr < a.M) {
            int ridx = a.use_map ? ((gr / a.rpt) * NPT + a.start + (gr % a.rpt)) : gr;
            Aptr = a.A + (size_t)ridx * 256;
        }
    }
    int brow = tid >> 4, bcol = (tid & 15) * 4;     // B tile loader

    for (int k0 = 0; k0 < 256; k0 += BK) {
        float4 av = make_float4(0.f,0.f,0.f,0.f);
        if (Aptr) av = *(const float4*)(Aptr + k0 + acol);
        As[acol+0][arow] = av.x; As[acol+1][arow] = av.y;
        As[acol+2][arow] = av.z; As[acol+3][arow] = av.w;
        float4 bv = *(const float4*)(a.B + (size_t)(k0 + brow) * a.N + n0 + bcol);
        *(float4*)&Bs[brow][bcol] = bv;
        __syncthreads();
        #pragma unroll
        for (int k = 0; k < BK; k++) {
            float4 ra = *(const float4*)&As[k][ty*4];
            float4 rb = *(const float4*)&Bs[k][tx*4];
            float am[4] = {ra.x, ra.y, ra.z, ra.w};
            float bn[4] = {rb.x, rb.y, rb.z, rb.w};
            #pragma unroll
            for (int i = 0; i < 4; i++)
                #pragma unroll
                for (int j = 0; j < 4; j++)
                    acc[i][j] = fmaf(am[i], bn[j], acc[i][j]);
        }
        __syncthreads();
    }
    #pragma unroll
    for (int i = 0; i < 4; i++) {
        int r = m0 + ty*4 + i;
        if (r >= a.M) continue;
        int ridx = a.use_map ? ((r / a.rpt) * NPT + a.start + (r % a.rpt)) : r;
        #pragma unroll
        for (int j = 0; j < 4; j++) {
            int col = n0 + tx*4 + j;
            float v = acc[i][j];
            if (EPI == 0) {
                a.Out[(size_t)r * a.N + col] = v;
            } else {
                float g = sigf(v + a.bias[col]);
                a.Out[(size_t)r * 256 + col] = g * a.Cst[(size_t)ridx * 256 + col];
            }
        }
    }
}

// ------------- leaf iou via precomputed table: iou = mean_s P[tok_s] -------------
__global__ void leaf_gather_kernel(const int* __restrict__ nf1, const int* __restrict__ nf2) {
    int b = blockIdx.z;
    const int* nf = b ? nf2 : nf1;
    int leaf = blockIdx.x;                 // 0..NLEAF-1
    int tree = leaf >> 8, ll = leaf & 255;
    int gnode = tree * NPT + LEAF_LOC0 + ll;
    __shared__ int toks[8];
    if (threadIdx.x < 8) toks[threadIdx.x] = nf[gnode * 8 + threadIdx.x];
    __syncthreads();
    const float* P = g_P + (size_t)b * VOCAB * IOUW;
    float* out = g_iou + (size_t)b * NLEAF * IOUW + (size_t)leaf * IOUW;
    #pragma unroll
    for (int jj = 0; jj < 3; jj++) {
        int j = threadIdx.x + jj * 256;
        float s = 0.f;
        #pragma unroll
        for (int t = 0; t < 8; t++) s += __ldg(&P[(size_t)toks[t] * IOUW + j]);
        out[j] = s * 0.125f;
    }
}

// ------------- activation: h,c from iou (+csum for internal levels) -------------
__global__ void act_kernel(const float* __restrict__ bi1, const float* __restrict__ bi2,
                           int start, int rpt, int use_csum) {
    int b = blockIdx.z;
    const float* bias = b ? bi2 : bi1;
    int r = blockIdx.x, j = threadIdx.x;
    const float* iou = g_iou + (size_t)b * NLEAF * IOUW + (size_t)r * IOUW;
    float i = iou[j]        + bias[j];
    float o = iou[256 + j]  + bias[256 + j];
    float u = iou[512 + j]  + bias[512 + j];
    float cs = use_csum ? g_cs[(size_t)b * T_TREES * 64 * HID + (size_t)r * HID + j] : 0.f;
    float c = sigf(i) * tanhf(u) + cs;
    float h = sigf(o) * tanhf(c);
    int g = (r / rpt) * NPT + start + (r % rpt);
    g_h[(size_t)b * NN * HID + (size_t)g * HID + j] = h;
    g_c[(size_t)b * NN * HID + (size_t)g * HID + j] = c;
}

// ------------- 4-child reduction: h_tild = sum h_child, c_sum = sum f*c --------
__global__ void reduce_kernel(int pcnt, int cstart, int ccnt) {
    int b = blockIdx.z, p = blockIdx.x, j = threadIdx.x;
    int tree = p / pcnt, lp = p % pcnt;
    size_t hb = (size_t)b * NN * HID + ((size_t)(tree * NPT + cstart + 4 * lp)) * HID + j;
    size_t cb = (size_t)b * NLEAF * HID + ((size_t)(tree * ccnt + 4 * lp)) * HID + j;
    float hs = 0.f, cs = 0.f;
    #pragma unroll
    for (int k = 0; k < 4; k++) { hs += g_h[hb + (size_t)k * HID]; cs += g_cc[cb + (size_t)k * HID]; }
    g_ht[(size_t)b * T_TREES * 64 * HID + (size_t)p * HID + j] = hs;
    g_cs[(size_t)b * T_TREES * 64 * HID + (size_t)p * HID + j] = cs;
}

// ------------- readout: mean-h per tree, relu, concat @ Wf, leaky, softmax -----
__global__ void readout_kernel(const float* __restrict__ Wf, const float* __restrict__ bf,
                               float* __restrict__ out) {
    int t = blockIdx.x, j = threadIdx.x;
    float s1 = 0.f, s2 = 0.f;
    size_t base = (size_t)t * NPT * HID + j;
    for (int n = 0; n < NPT; n++) {
        s1 += g_h[base + (size_t)n * HID];
        s2 += g_h[(size_t)NN * HID + base + (size_t)n * HID];
    }
    float m1 = fmaxf(s1 * (1.0f / NPT), 0.f);
    float m2 = fmaxf(s2 * (1.0f / NPT), 0.f);
    float p0 = m1 * Wf[j * 2 + 0] + m2 * Wf[(256 + j) * 2 + 0];
    float p1 = m1 * Wf[j * 2 + 1] + m2 * Wf[(256 + j) * 2 + 1];
    __shared__ float sm0[256], sm1[256];
    sm0[j] = p0; sm1[j] = p1; __syncthreads();
    for (int s = 128; s > 0; s >>= 1) {
        if (j < s) { sm0[j] += sm0[j + s]; sm1[j] += sm1[j + s]; }
        __syncthreads();
    }
    if (j == 0) {
        float l0 = sm0[0] + bf[0], l1 = sm1[0] + bf[1];
        l0 = (l0 >= 0.f) ? l0 : 0.01f * l0;
        l1 = (l1 >= 0.f) ? l1 : 0.01f * l1;
        float mx = fmaxf(l0, l1);
        float e0 = __expf(l0 - mx), e1 = __expf(l1 - mx);
        float inv = 1.0f / (e0 + e1);
        out[t * 2 + 0] = e0 * inv;
        out[t * 2 + 1] = e1 * inv;
    }
}

// -------------------------------- launch --------------------------------------
extern "C" void kernel_launch(void* const* d_in, const int* in_sizes, int n_in,
                              void* d_out, int out_size) {
    const int*   nf1   = (const int*)  d_in[0];
    const int*   nf2   = (const int*)  d_in[1];
    const float* emb1  = (const float*)d_in[2];
    const float* emb2  = (const float*)d_in[3];
    const float* Wiou1 = (const float*)d_in[4];
    const float* Wiou2 = (const float*)d_in[5];
    const float* Uiou1 = (const float*)d_in[6];
    const float* Uiou2 = (const float*)d_in[7];
    const float* UfW1  = (const float*)d_in[8];
    const float* Ufb1  = (const float*)d_in[9];
    const float* UfW2  = (const float*)d_in[10];
    const float* Ufb2  = (const float*)d_in[11];
    const float* biou1 = (const float*)d_in[12];
    const float* biou2 = (const float*)d_in[13];
    const float* Wf    = (const float*)d_in[14];
    const float* bf    = (const float*)d_in[15];
    float* out = (float*)d_out;

    float *P, *iouS, *h, *c, *cc, *ht;
    cudaGetSymbolAddress((void**)&P,    g_P);
    cudaGetSymbolAddress((void**)&iouS, g_iou);
    cudaGetSymbolAddress((void**)&h,    g_h);
    cudaGetSymbolAddress((void**)&c,    g_c);
    cudaGetSymbolAddress((void**)&cc,   g_cc);
    cudaGetSymbolAddress((void**)&ht,   g_ht);

    const size_t Poff = (size_t)VOCAB * IOUW;
    const size_t Hoff = (size_t)NN * HID;
    const size_t Coff = (size_t)NLEAF * HID;
    const size_t Ioff = (size_t)NLEAF * IOUW;
    const size_t Toff = (size_t)T_TREES * 64 * HID;

    // 1) token tables: P[b] = emb[b] @ W_iou[b]   [10000,256]@[256,768]
    {
        GemmArgs a0{emb1, Wiou1, nullptr, nullptr, P,        VOCAB, IOUW, 0, 1, 0};
        GemmArgs a1{emb2, Wiou2, nullptr, nullptr, P + Poff, VOCAB, IOUW, 0, 1, 0};
        gemm_k<0><<<dim3(IOUW/64, (VOCAB + 63)/64, 2), 256>>>(a0, a1);
    }
    // 2) leaf iou = mean over 8 subtokens of P rows
    leaf_gather_kernel<<<dim3(NLEAF, 1, 2), 256>>>(nf1, nf2);
    // 3) leaf activation -> h,c (local nodes 85..340)
    act_kernel<<<dim3(NLEAF, 1, 2), 256>>>(biou1, biou2, LEAF_LOC0, LPT, 0);

    // level tables: parent start/count, child start/count (local, per tree)
    const int ps_[4]   = {21, 5, 1, 0};
    const int pcnt_[4] = {64, 16, 4, 1};
    const int cs_[4]   = {85, 21, 5, 1};
    const int ccnt_[4] = {256, 64, 16, 4};

    for (int L = 0; L < 4; L++) {
        int Mc = T_TREES * ccnt_[L];
        int Mp = T_TREES * pcnt_[L];
        // 4a) per-edge forget gate: cc = sigmoid(h_child @ Uf_W + Uf_b) * c_child
        {
            GemmArgs a0{h,        UfW1, Ufb1, c,        cc,        Mc, HID, cs_[L], ccnt_[L], 1};
            GemmArgs a1{h + Hoff, UfW2, Ufb2, c + Hoff, cc + Coff, Mc, HID, cs_[L], ccnt_[L], 1};
            gemm_k<1><<<dim3(HID/64, (Mc + 63)/64, 2), 256>>>(a0, a1);
        }
        // 4b) 4-child reduction -> h_tild, c_sum
        reduce_kernel<<<dim3(Mp, 1, 2), 256>>>(pcnt_[L], cs_[L], ccnt_[L]);
        // 4c) parent iou = h_tild @ U_iou
        {
            GemmArgs a0{ht,        Uiou1, nullptr, nullptr, iouS,        Mp, IOUW, 0, 1, 0};
            GemmArgs a1{ht + Toff, Uiou2, nullptr, nullptr, iouS + Ioff, Mp, IOUW, 0, 1, 0};
            gemm_k<0><<<dim3(IOUW/64, (Mp + 63)/64, 2), 256>>>(a0, a1);
        }
        // 4d) parent activation (with c_sum)
        act_kernel<<<dim3(Mp, 1, 2), 256>>>(biou1, biou2, ps_[L], pcnt_[L], 1);
    }

    // 5) readout: per-tree mean(h), relu, concat @ Wf + bf, leaky_relu, softmax
    readout_kernel<<<T_TREES, 256>>>(Wf, bf, out);
}

// round 3
// speedup vs baseline: 1.1695x; 1.1695x over previous
#include <cuda_runtime.h>
#include <math.h>

// ---------------- problem constants (structure is deterministic) ----------------
#define T_TREES   150
#define NPT       341          // nodes per tree (level-order, node0 = root)
#define NN        (T_TREES*NPT)
#define HID       256
#define IOUW      768
#define VOCAB     10000
#define LEAF_LOC0 85           // leaves are local nodes [85, 341)
#define LPT       256          // leaves per tree
#define NLEAF     (T_TREES*LPT)
#define NINT      (T_TREES*64) // max parents per level (9600)

// ---------------- scratch (device globals; no allocation allowed) ----------------
__device__ float g_P   [2u*VOCAB*IOUW];   // emb @ W_iou tables
__device__ float g_iou [2u*NINT*IOUW];    // iou scratch (internal nodes only)
__device__ float g_h   [2u*NN*HID];
__device__ float g_c   [2u*NN*HID];
__device__ float g_cc  [2u*NLEAF*HID];    // f * c_child per edge (compact child order)
__device__ float g_ht  [2u*NINT*HID];     // h_tild
__device__ float g_cs  [2u*NINT*HID];     // c_sum

__device__ __forceinline__ float sigf(float x) { return 1.0f/(1.0f+__expf(-x)); }
__device__ __forceinline__ float tanh_fast(float x) {
    float y; asm("tanh.approx.f32 %0, %1;" : "=f"(y) : "f"(x)); return y;
}

// ---------------- f32x2 packed helpers (Blackwell FFMA2 path) -------------------
__device__ __forceinline__ unsigned long long dup2(float x) {
    unsigned long long r; unsigned u = __float_as_uint(x);
    asm("mov.b64 %0, {%1, %1};" : "=l"(r) : "r"(u));
    return r;
}
__device__ __forceinline__ void fma2(unsigned long long& d, unsigned long long a,
                                     unsigned long long b) {
    asm("fma.rn.f32x2 %0, %1, %2, %0;" : "+l"(d) : "l"(a), "l"(b));
}
__device__ __forceinline__ float2 unp(unsigned long long v) {
    unsigned lo, hi;
    asm("mov.b64 {%0, %1}, %2;" : "=r"(lo), "=r"(hi) : "l"(v));
    return make_float2(__uint_as_float(lo), __uint_as_float(hi));
}

// ---------------- fp32 GEMM, K=256 fixed, C = A@B (+epilogue) -------------------
// BM=BN=128, BK=16, 256 threads, 8x8 microtile, packed f32x2 accumulation.
// A rows optionally mapped into node array: ridx = (r/rpt)*NPT + start + r%rpt
struct GemmArgs {
    const float* A; const float* B; const float* bias; const float* Cst;
    float* Out; int M; int N; int start; int rpt; int use_map;
};

__device__ __forceinline__ int rmap(const GemmArgs& a, int r) {
    return a.use_map ? ((r / a.rpt) * NPT + a.start + (r % a.rpt)) : r;
}

template<int EPI>   // 0: Out[r*N+col] = acc ; 1: fgate: Out[r*256+col]=sig(acc+bias)*Cst[ridx]
__global__ __launch_bounds__(256, 2)
void gemm_k(GemmArgs a0, GemmArgs a1) {
    GemmArgs a = (blockIdx.z == 0) ? a0 : a1;
    __shared__ float As[16][132];
    __shared__ float Bs[16][132];
    int tid = threadIdx.x;
    int tx = tid & 15, ty = tid >> 4;
    int m0 = blockIdx.y * 128, n0 = blockIdx.x * 128;

    // A loader: rows arow, arow+64; k chunk acol..acol+3
    int arow = tid >> 2;
    int acol = (tid & 3) * 4;
    const float *Ap0 = nullptr, *Ap1 = nullptr;
    {
        int gr0 = m0 + arow, gr1 = m0 + arow + 64;
        if (gr0 < a.M) Ap0 = a.A + (size_t)rmap(a, gr0) * 256 + acol;
        if (gr1 < a.M) Ap1 = a.A + (size_t)rmap(a, gr1) * 256 + acol;
    }
    // B loader: rows brow, brow+8; cols bcol..bcol+3 (contiguous float4)
    int brow = tid >> 5;
    int bcol = (tid & 31) * 4;
    const float* Bp = a.B + (size_t)brow * a.N + n0 + bcol;

    unsigned long long acc[8][4];
    #pragma unroll
    for (int i = 0; i < 8; i++)
        #pragma unroll
        for (int j = 0; j < 4; j++) acc[i][j] = 0ull;

    for (int k0 = 0; k0 < 256; k0 += 16) {
        float4 z = make_float4(0.f,0.f,0.f,0.f);
        float4 av0 = Ap0 ? *(const float4*)(Ap0 + k0) : z;
        float4 av1 = Ap1 ? *(const float4*)(Ap1 + k0) : z;
        float4 bv0 = *(const float4*)(Bp + (size_t)k0 * a.N);
        float4 bv1 = *(const float4*)(Bp + (size_t)(k0 + 8) * a.N);
        As[acol+0][arow] = av0.x; As[acol+1][arow] = av0.y;
        As[acol+2][arow] = av0.z; As[acol+3][arow] = av0.w;
        As[acol+0][arow+64] = av1.x; As[acol+1][arow+64] = av1.y;
        As[acol+2][arow+64] = av1.z; As[acol+3][arow+64] = av1.w;
        *(float4*)&Bs[brow][bcol]     = bv0;
        *(float4*)&Bs[brow + 8][bcol] = bv1;
        __syncthreads();
        #pragma unroll
        for (int k = 0; k < 16; k++) {
            float4 af0 = *(const float4*)&As[k][ty*8];
            float4 af1 = *(const float4*)&As[k][ty*8 + 4];
            ulonglong2 bq0 = *(const ulonglong2*)&Bs[k][tx*8];
            ulonglong2 bq1 = *(const ulonglong2*)&Bs[k][tx*8 + 4];
            unsigned long long bp_[4] = {bq0.x, bq0.y, bq1.x, bq1.y};
            float am[8] = {af0.x, af0.y, af0.z, af0.w, af1.x, af1.y, af1.z, af1.w};
            #pragma unroll
            for (int i = 0; i < 8; i++) {
                unsigned long long ap = dup2(am[i]);
                #pragma unroll
                for (int j = 0; j < 4; j++) fma2(acc[i][j], ap, bp_[j]);
            }
        }
        __syncthreads();
    }

    int col0 = n0 + tx * 8;
    if (EPI == 1) {
        float4 bb0 = *(const float4*)&a.bias[col0];
        float4 bb1 = *(const float4*)&a.bias[col0 + 4];
        float bias8[8] = {bb0.x,bb0.y,bb0.z,bb0.w,bb1.x,bb1.y,bb1.z,bb1.w};
        #pragma unroll
        for (int i = 0; i < 8; i++) {
            int r = m0 + ty*8 + i;
            if (r >= a.M) continue;
            int ridx = rmap(a, r);
            const float* cst = a.Cst + (size_t)ridx * 256 + col0;
            float4 c0 = *(const float4*)(cst);
            float4 c1 = *(const float4*)(cst + 4);
            float cv[8] = {c0.x,c0.y,c0.z,c0.w,c1.x,c1.y,c1.z,c1.w};
            float o[8];
            #pragma unroll
            for (int j = 0; j < 4; j++) {
                float2 v = unp(acc[i][j]);
                o[2*j]   = sigf(v.x + bias8[2*j])   * cv[2*j];
                o[2*j+1] = sigf(v.y + bias8[2*j+1]) * cv[2*j+1];
            }
            float* dst = a.Out + (size_t)r * 256 + col0;
            *(float4*)dst       = make_float4(o[0],o[1],o[2],o[3]);
            *(float4*)(dst + 4) = make_float4(o[4],o[5],o[6],o[7]);
        }
    } else {
        #pragma unroll
        for (int i = 0; i < 8; i++) {
            int r = m0 + ty*8 + i;
            if (r >= a.M) continue;
            float2 p0 = unp(acc[i][0]), p1 = unp(acc[i][1]);
            float2 p2 = unp(acc[i][2]), p3 = unp(acc[i][3]);
            float* dst = a.Out + (size_t)r * a.N + col0;
            *(float4*)dst       = make_float4(p0.x,p0.y,p1.x,p1.y);
            *(float4*)(dst + 4) = make_float4(p2.x,p2.y,p3.x,p3.y);
        }
    }
}

// ------- fused leaf: iou = mean_s P[tok_s] cols (j,256+j,512+j) -> activation ----
__global__ void leaf_act_kernel(const int* __restrict__ nf1, const int* __restrict__ nf2,
                                const float* __restrict__ bi1, const float* __restrict__ bi2) {
    int b = blockIdx.z;
    const int* nf = b ? nf2 : nf1;
    const float* bias = b ? bi2 : bi1;
    int leaf = blockIdx.x;
    int tree = leaf >> 8, ll = leaf & 255;
    int gnode = tree * NPT + LEAF_LOC0 + ll;
    __shared__ int toks[8];
    if (threadIdx.x < 8) toks[threadIdx.x] = nf[gnode * 8 + threadIdx.x];
    __syncthreads();
    const float* P = g_P + (size_t)b * VOCAB * IOUW;
    int j = threadIdx.x;
    float si = 0.f, so = 0.f, su = 0.f;
    #pragma unroll
    for (int t = 0; t < 8; t++) {
        const float* row = P + (size_t)toks[t] * IOUW;
        si += __ldg(row + j);
        so += __ldg(row + 256 + j);
        su += __ldg(row + 512 + j);
    }
    float iv = si * 0.125f + bias[j];
    float ov = so * 0.125f + bias[256 + j];
    float uv = su * 0.125f + bias[512 + j];
    float c = sigf(iv) * tanh_fast(uv);
    float h = sigf(ov) * tanh_fast(c);
    g_h[(size_t)b * NN * HID + (size_t)gnode * HID + j] = h;
    g_c[(size_t)b * NN * HID + (size_t)gnode * HID + j] = c;
}

// ------------- activation for internal nodes (reads g_iou + g_cs) ---------------
__global__ void act_kernel(const float* __restrict__ bi1, const float* __restrict__ bi2,
                           int start, int rpt) {
    int b = blockIdx.z;
    const float* bias = b ? bi2 : bi1;
    int r = blockIdx.x, j = threadIdx.x;
    const float* iou = g_iou + (size_t)b * NINT * IOUW + (size_t)r * IOUW;
    float iv = iou[j]       + bias[j];
    float ov = iou[256 + j] + bias[256 + j];
    float uv = iou[512 + j] + bias[512 + j];
    float cs = g_cs[(size_t)b * NINT * HID + (size_t)r * HID + j];
    float c = sigf(iv) * tanh_fast(uv) + cs;
    float h = sigf(ov) * tanh_fast(c);
    int g = (r / rpt) * NPT + start + (r % rpt);
    g_h[(size_t)b * NN * HID + (size_t)g * HID + j] = h;
    g_c[(size_t)b * NN * HID + (size_t)g * HID + j] = c;
}

// ------------- 4-child reduction: h_tild = sum h_child, c_sum = sum f*c --------
__global__ void reduce_kernel(int pcnt, int cstart, int ccnt) {
    int b = blockIdx.z, p = blockIdx.x, j = threadIdx.x;
    int tree = p / pcnt, lp = p % pcnt;
    size_t hb = (size_t)b * NN * HID + ((size_t)(tree * NPT + cstart + 4 * lp)) * HID + j;
    size_t cb = (size_t)b * NLEAF * HID + ((size_t)(tree * ccnt + 4 * lp)) * HID + j;
    float hs = 0.f, cs = 0.f;
    #pragma unroll
    for (int k = 0; k < 4; k++) { hs += g_h[hb + (size_t)k * HID]; cs += g_cc[cb + (size_t)k * HID]; }
    g_ht[(size_t)b * NINT * HID + (size_t)p * HID + j] = hs;
    g_cs[(size_t)b * NINT * HID + (size_t)p * HID + j] = cs;
}

// ------------- readout: mean-h per tree, relu, concat @ Wf, leaky, softmax -----
__global__ void readout_kernel(const float* __restrict__ Wf, const float* __restrict__ bf,
                               float* __restrict__ out) {
    int t = blockIdx.x, j = threadIdx.x;
    float s1 = 0.f, s2 = 0.f;
    size_t base = (size_t)t * NPT * HID + j;
    for (int n = 0; n < NPT; n++) {
        s1 += g_h[base + (size_t)n * HID];
        s2 += g_h[(size_t)NN * HID + base + (size_t)n * HID];
    }
    float m1 = fmaxf(s1 * (1.0f / NPT), 0.f);
    float m2 = fmaxf(s2 * (1.0f / NPT), 0.f);
    float p0 = m1 * Wf[j * 2 + 0] + m2 * Wf[(256 + j) * 2 + 0];
    float p1 = m1 * Wf[j * 2 + 1] + m2 * Wf[(256 + j) * 2 + 1];
    __shared__ float sm0[256], sm1[256];
    sm0[j] = p0; sm1[j] = p1; __syncthreads();
    for (int s = 128; s > 0; s >>= 1) {
        if (j < s) { sm0[j] += sm0[j + s]; sm1[j] += sm1[j + s]; }
        __syncthreads();
    }
    if (j == 0) {
        float l0 = sm0[0] + bf[0], l1 = sm1[0] + bf[1];
        l0 = (l0 >= 0.f) ? l0 : 0.01f * l0;
        l1 = (l1 >= 0.f) ? l1 : 0.01f * l1;
        float mx = fmaxf(l0, l1);
        float e0 = __expf(l0 - mx), e1 = __expf(l1 - mx);
        float inv = 1.0f / (e0 + e1);
        out[t * 2 + 0] = e0 * inv;
        out[t * 2 + 1] = e1 * inv;
    }
}

// -------------------------------- launch --------------------------------------
extern "C" void kernel_launch(void* const* d_in, const int* in_sizes, int n_in,
                              void* d_out, int out_size) {
    const int*   nf1   = (const int*)  d_in[0];
    const int*   nf2   = (const int*)  d_in[1];
    const float* emb1  = (const float*)d_in[2];
    const float* emb2  = (const float*)d_in[3];
    const float* Wiou1 = (const float*)d_in[4];
    const float* Wiou2 = (const float*)d_in[5];
    const float* Uiou1 = (const float*)d_in[6];
    const float* Uiou2 = (const float*)d_in[7];
    const float* UfW1  = (const float*)d_in[8];
    const float* Ufb1  = (const float*)d_in[9];
    const float* UfW2  = (const float*)d_in[10];
    const float* Ufb2  = (const float*)d_in[11];
    const float* biou1 = (const float*)d_in[12];
    const float* biou2 = (const float*)d_in[13];
    const float* Wf    = (const float*)d_in[14];
    const float* bf    = (const float*)d_in[15];
    float* out = (float*)d_out;

    float *P, *iouS, *h, *c, *cc, *ht;
    cudaGetSymbolAddress((void**)&P,    g_P);
    cudaGetSymbolAddress((void**)&iouS, g_iou);
    cudaGetSymbolAddress((void**)&h,    g_h);
    cudaGetSymbolAddress((void**)&c,    g_c);
    cudaGetSymbolAddress((void**)&cc,   g_cc);
    cudaGetSymbolAddress((void**)&ht,   g_ht);

    const size_t Poff = (size_t)VOCAB * IOUW;
    const size_t Hoff = (size_t)NN * HID;
    const size_t Coff = (size_t)NLEAF * HID;
    const size_t Ioff = (size_t)NINT * IOUW;
    const size_t Toff = (size_t)NINT * HID;

    // 1) token tables: P[b] = emb[b] @ W_iou[b]   [10000,256]@[256,768]
    {
        GemmArgs a0{emb1, Wiou1, nullptr, nullptr, P,        VOCAB, IOUW, 0, 1, 0};
        GemmArgs a1{emb2, Wiou2, nullptr, nullptr, P + Poff, VOCAB, IOUW, 0, 1, 0};
        gemm_k<0><<<dim3(IOUW/128, (VOCAB + 127)/128, 2), 256>>>(a0, a1);
    }
    // 2) fused leaf gather + activation -> h,c (local nodes 85..340)
    leaf_act_kernel<<<dim3(NLEAF, 1, 2), 256>>>(nf1, nf2, biou1, biou2);

    // level tables: parent start/count, child start/count (local, per tree)
    const int ps_[4]   = {21, 5, 1, 0};
    const int pcnt_[4] = {64, 16, 4, 1};
    const int cs_[4]   = {85, 21, 5, 1};
    const int ccnt_[4] = {256, 64, 16, 4};

    for (int L = 0; L < 4; L++) {
        int Mc = T_TREES * ccnt_[L];
        int Mp = T_TREES * pcnt_[L];
        // 4a) per-edge forget gate: cc = sigmoid(h_child @ Uf_W + Uf_b) * c_child
        {
            GemmArgs a0{h,        UfW1, Ufb1, c,        cc,        Mc, HID, cs_[L], ccnt_[L], 1};
            GemmArgs a1{h + Hoff, UfW2, Ufb2, c + Hoff, cc + Coff, Mc, HID, cs_[L], ccnt_[L], 1};
            gemm_k<1><<<dim3(HID/128, (Mc + 127)/128, 2), 256>>>(a0, a1);
        }
        // 4b) 4-child reduction -> h_tild, c_sum
        reduce_kernel<<<dim3(Mp, 1, 2), 256>>>(pcnt_[L], cs_[L], ccnt_[L]);
        // 4c) parent iou = h_tild @ U_iou
        {
            GemmArgs a0{ht,        Uiou1, nullptr, nullptr, iouS,        Mp, IOUW, 0, 1, 0};
            GemmArgs a1{ht + Toff, Uiou2, nullptr, nullptr, iouS + Ioff, Mp, IOUW, 0, 1, 0};
            gemm_k<0><<<dim3(IOUW/128, (Mp + 127)/128, 2), 256>>>(a0, a1);
        }
        // 4d) parent activation (with c_sum)
        act_kernel<<<dim3(Mp, 1, 2), 256>>>(biou1, biou2, ps_[L], pcnt_[L]);
    }

    // 5) readout: per-tree mean(h), relu, concat @ Wf + bf, leaky_relu, softmax
    readout_kernel<<<T_TREES, 256>>>(Wf, bf, out);
}

// round 5
// speedup vs baseline: 1.7839x; 1.5254x over previous
#include <cuda_runtime.h>
#include <math.h>
#include <stdint.h>

// ---------------- problem constants (structure is deterministic) ----------------
#define T_TREES   150
#define NPT       341          // nodes per tree (level-order, node0 = root)
#define NN        (T_TREES*NPT)
#define HID       256
#define IOUW      768
#define VOCAB     10000
#define LEAF_LOC0 85           // leaves are local nodes [85, 341)
#define LPT       256          // leaves per tree
#define NLEAF     (T_TREES*LPT)
#define NINT      (T_TREES*64) // max parents per level (9600)

// ---------------- scratch (device globals; no allocation allowed) ----------------
__device__ float g_P   [2u*VOCAB*IOUW];   // emb @ W_iou tables
__device__ float g_iou [2u*NINT*IOUW];    // iou scratch (internal nodes only)
__device__ float g_h   [2u*NN*HID];
__device__ float g_c   [2u*NN*HID];
__device__ float g_cc  [2u*NLEAF*HID];    // f * c_child per edge (compact child order)
__device__ float g_ht  [2u*NINT*HID];     // h_tild
__device__ float g_cs  [2u*NINT*HID];     // c_sum
__device__ float g_UfT [2u*256*256];      // Uf_W^T  [N=256,K=256] row-major
__device__ float g_UiT [2u*768*256];      // U_iou^T [N=768,K=256]
__device__ float g_WiT [2u*768*256];      // W_iou^T [N=768,K=256]

__device__ __forceinline__ float sigf(float x) { return 1.0f/(1.0f+__expf(-x)); }
__device__ __forceinline__ float tanh_fast(float x) {
    float y; asm("tanh.approx.f32 %0, %1;" : "=f"(y) : "f"(x)); return y;
}
__device__ __forceinline__ unsigned tf32b(float x) {
    unsigned u; asm("cvt.rna.tf32.f32 %0, %1;" : "=r"(u) : "f"(x)); return u;
}

// ---------------- tf32 mma.sync GEMM: C[M,Ntot] = A[M,256] @ Bt[Ntot,256]^T ------
// BM=BN=128, BK=32, 256 threads = 8 warps (2 M x 4 N), warp tile 64x32.
struct GemmArgs {
    const float* A; const float* Bt; const float* bias; const float* Cst;
    float* Out; int M; int Ntot; int start; int rpt; int use_map;
};
__device__ __forceinline__ int rmap(const GemmArgs& a, int r) {
    return a.use_map ? ((r / a.rpt) * NPT + a.start + (r % a.rpt)) : r;
}

#define SMS 36   // smem row stride (floats): conflict-free for mma fragment pattern

template<int EPI>   // 0: plain store ; 1: fgate: Out[r*256+c]=sig(acc+bias[c])*Cst[ridx*256+c]
__global__ __launch_bounds__(256, 2)
void mma_gemm(GemmArgs a0, GemmArgs a1) {
    GemmArgs a = (blockIdx.z == 0) ? a0 : a1;
    __shared__ unsigned As[128][SMS];
    __shared__ unsigned Bs[128][SMS];
    int tid = threadIdx.x, lane = tid & 31, wid = tid >> 5;
    int wm = wid >> 2, wn = wid & 3;
    int qr = lane >> 2, qc = lane & 3;
    int m0 = blockIdx.y * 128, n0 = blockIdx.x * 128;

    // loaders: thread -> row tid>>1, k-half (tid&1)*16
    int lrow = tid >> 1, lkh = (tid & 1) * 16;
    int gr = m0 + lrow;
    const float* Ap = nullptr;
    if (gr < a.M) Ap = a.A + (size_t)rmap(a, gr) * 256 + lkh;
    const float* Bp = a.Bt + (size_t)(n0 + lrow) * 256 + lkh;   // Ntot % 128 == 0

    float acc[4][4][4];
    #pragma unroll
    for (int mt = 0; mt < 4; mt++)
        #pragma unroll
        for (int nt = 0; nt < 4; nt++)
            #pragma unroll
            for (int i = 0; i < 4; i++) acc[mt][nt][i] = 0.f;

    for (int kc = 0; kc < 256; kc += 32) {
        #pragma unroll
        for (int v = 0; v < 4; v++) {
            float4 av = make_float4(0.f,0.f,0.f,0.f);
            if (Ap) av = *(const float4*)(Ap + kc + v * 4);
            float4 bv = *(const float4*)(Bp + kc + v * 4);
            uint4 au = make_uint4(tf32b(av.x), tf32b(av.y), tf32b(av.z), tf32b(av.w));
            uint4 bu = make_uint4(tf32b(bv.x), tf32b(bv.y), tf32b(bv.z), tf32b(bv.w));
            *(uint4*)&As[lrow][lkh + v * 4] = au;
            *(uint4*)&Bs[lrow][lkh + v * 4] = bu;
        }
        __syncthreads();
        #pragma unroll
        for (int ks = 0; ks < 4; ks++) {
            int k0 = ks * 8;
            unsigned af[4][4], bf[4][2];
            #pragma unroll
            for (int mt = 0; mt < 4; mt++) {
                int ra = wm * 64 + mt * 16 + qr;
                af[mt][0] = As[ra    ][k0 + qc];
                af[mt][1] = As[ra + 8][k0 + qc];
                af[mt][2] = As[ra    ][k0 + qc + 4];
                af[mt][3] = As[ra + 8][k0 + qc + 4];
            }
            #pragma unroll
            for (int nt = 0; nt < 4; nt++) {
                int rb = wn * 32 + nt * 8 + qr;
                bf[nt][0] = Bs[rb][k0 + qc];
                bf[nt][1] = Bs[rb][k0 + qc + 4];
            }
            #pragma unroll
            for (int mt = 0; mt < 4; mt++)
                #pragma unroll
                for (int nt = 0; nt < 4; nt++) {
                    float* d = acc[mt][nt];
                    asm volatile(
                        "mma.sync.aligned.m16n8k8.row.col.f32.tf32.tf32.f32 "
                        "{%0,%1,%2,%3}, {%4,%5,%6,%7}, {%8,%9}, {%0,%1,%2,%3};"
                        : "+f"(d[0]), "+f"(d[1]), "+f"(d[2]), "+f"(d[3])
                        : "r"(af[mt][0]), "r"(af[mt][1]), "r"(af[mt][2]), "r"(af[mt][3]),
                          "r"(bf[nt][0]), "r"(bf[nt][1]));
                }
        }
        __syncthreads();
    }

    // epilogue: thread owns rows (qr, qr+8) of each m-tile, cols 2qc,2qc+1 per n-tile
    #pragma unroll
    for (int mt = 0; mt < 4; mt++) {
        #pragma unroll
        for (int half = 0; half < 2; half++) {
            int r = m0 + wm * 64 + mt * 16 + qr + half * 8;
            if (r >= a.M) continue;
            int ridx = rmap(a, r);
            #pragma unroll
            for (int nt = 0; nt < 4; nt++) {
                int col = n0 + wn * 32 + nt * 8 + qc * 2;
                float v0 = acc[mt][nt][half * 2 + 0];
                float v1 = acc[mt][nt][half * 2 + 1];
                if (EPI == 1) {
                    float b0 = __ldg(&a.bias[col]), b1 = __ldg(&a.bias[col + 1]);
                    const float* cst = a.Cst + (size_t)ridx * 256 + col;
                    float2 o;
                    o.x = sigf(v0 + b0) * cst[0];
                    o.y = sigf(v1 + b1) * cst[1];
                    *(float2*)(a.Out + (size_t)r * 256 + col) = o;
                } else {
                    *(float2*)(a.Out + (size_t)r * a.Ntot + col) = make_float2(v0, v1);
                }
            }
        }
    }
}

// ---------------- weight transpose: S[256,N] -> D[N,256] ------------------------
struct TPair { const float* s; float* d; int n; };
__global__ void transpose_k(TPair p0, TPair p1, TPair p2, TPair p3, TPair p4, TPair p5) {
    TPair p;
    switch (blockIdx.z) {
        case 0: p = p0; break; case 1: p = p1; break; case 2: p = p2; break;
        case 3: p = p3; break; case 4: p = p4; break; default: p = p5; break;
    }
    int x0 = blockIdx.x * 32;
    if (x0 >= p.n) return;
    int y0 = blockIdx.y * 32;
    __shared__ float t[32][33];
    #pragma unroll
    for (int s = 0; s < 32; s += 8)
        t[threadIdx.y + s][threadIdx.x] = p.s[(size_t)(y0 + threadIdx.y + s) * p.n + x0 + threadIdx.x];
    __syncthreads();
    #pragma unroll
    for (int s = 0; s < 32; s += 8)
        p.d[(size_t)(x0 + threadIdx.y + s) * 256 + y0 + threadIdx.x] = t[threadIdx.x][threadIdx.y + s];
}

// ------- fused leaf: iou = mean_s P[tok_s] cols (j,256+j,512+j) -> activation ----
__global__ void leaf_act_kernel(const int* __restrict__ nf1, const int* __restrict__ nf2,
                                const float* __restrict__ bi1, const float* __restrict__ bi2) {
    int b = blockIdx.z;
    const int* nf = b ? nf2 : nf1;
    const float* bias = b ? bi2 : bi1;
    int leaf = blockIdx.x;
    int tree = leaf >> 8, ll = leaf & 255;
    int gnode = tree * NPT + LEAF_LOC0 + ll;
    __shared__ int toks[8];
    if (threadIdx.x < 8) toks[threadIdx.x] = nf[gnode * 8 + threadIdx.x];
    __syncthreads();
    const float* P = g_P + (size_t)b * VOCAB * IOUW;
    int j = threadIdx.x;
    float si = 0.f, so = 0.f, su = 0.f;
    #pragma unroll
    for (int t = 0; t < 8; t++) {
        const float* row = P + (size_t)toks[t] * IOUW;
        si += __ldg(row + j);
        so += __ldg(row + 256 + j);
        su += __ldg(row + 512 + j);
    }
    float iv = si * 0.125f + bias[j];
    float ov = so * 0.125f + bias[256 + j];
    float uv = su * 0.125f + bias[512 + j];
    float c = sigf(iv) * tanh_fast(uv);
    float h = sigf(ov) * tanh_fast(c);
    g_h[(size_t)b * NN * HID + (size_t)gnode * HID + j] = h;
    g_c[(size_t)b * NN * HID + (size_t)gnode * HID + j] = c;
}

// ------------- activation for internal nodes (reads g_iou + g_cs) ---------------
__global__ void act_kernel(const float* __restrict__ bi1, const float* __restrict__ bi2,
                           int start, int rpt) {
    int b = blockIdx.z;
    const float* bias = b ? bi2 : bi1;
    int r = blockIdx.x, j = threadIdx.x;
    const float* iou = g_iou + (size_t)b * NINT * IOUW + (size_t)r * IOUW;
    float iv = iou[j]       + bias[j];
    float ov = iou[256 + j] + bias[256 + j];
    float uv = iou[512 + j] + bias[512 + j];
    float cs = g_cs[(size_t)b * NINT * HID + (size_t)r * HID + j];
    float c = sigf(iv) * tanh_fast(uv) + cs;
    float h = sigf(ov) * tanh_fast(c);
    int g = (r / rpt) * NPT + start + (r % rpt);
    g_h[(size_t)b * NN * HID + (size_t)g * HID + j] = h;
    g_c[(size_t)b * NN * HID + (size_t)g * HID + j] = c;
}

// ------------- 4-child reduction: h_tild = sum h_child, c_sum = sum f*c --------
__global__ void reduce_kernel(int pcnt, int cstart, int ccnt) {
    int b = blockIdx.z, p = blockIdx.x, j = threadIdx.x;
    int tree = p / pcnt, lp = p % pcnt;
    size_t hb = (size_t)b * NN * HID + ((size_t)(tree * NPT + cstart + 4 * lp)) * HID + j;
    size_t cb = (size_t)b * NLEAF * HID + ((size_t)(tree * ccnt + 4 * lp)) * HID + j;
    float hs = 0.f, cs = 0.f;
    #pragma unroll
    for (int k = 0; k < 4; k++) { hs += g_h[hb + (size_t)k * HID]; cs += g_cc[cb + (size_t)k * HID]; }
    g_ht[(size_t)b * NINT * HID + (size_t)p * HID + j] = hs;
    g_cs[(size_t)b * NINT * HID + (size_t)p * HID + j] = cs;
}

// ------------- readout: mean-h per tree, relu, concat @ Wf, leaky, softmax -----
__global__ void readout_kernel(const float* __restrict__ Wf, const float* __restrict__ bf,
                               float* __restrict__ out) {
    int t = blockIdx.x, j = threadIdx.x;
    float s1 = 0.f, s2 = 0.f;
    size_t base = (size_t)t * NPT * HID + j;
    for (int n = 0; n < NPT; n++) {
        s1 += g_h[base + (size_t)n * HID];
        s2 += g_h[(size_t)NN * HID + base + (size_t)n * HID];
    }
    float m1 = fmaxf(s1 * (1.0f / NPT), 0.f);
    float m2 = fmaxf(s2 * (1.0f / NPT), 0.f);
    float p0 = m1 * Wf[j * 2 + 0] + m2 * Wf[(256 + j) * 2 + 0];
    float p1 = m1 * Wf[j * 2 + 1] + m2 * Wf[(256 + j) * 2 + 1];
    __shared__ float sm0[256], sm1[256];
    sm0[j] = p0; sm1[j] = p1; __syncthreads();
    for (int s = 128; s > 0; s >>= 1) {
        if (j < s) { sm0[j] += sm0[j + s]; sm1[j] += sm1[j + s]; }
        __syncthreads();
    }
    if (j == 0) {
        float l0 = sm0[0] + bf[0], l1 = sm1[0] + bf[1];
        l0 = (l0 >= 0.f) ? l0 : 0.01f * l0;
        l1 = (l1 >= 0.f) ? l1 : 0.01f * l1;
        float mx = fmaxf(l0, l1);
        float e0 = __expf(l0 - mx), e1 = __expf(l1 - mx);
        float inv = 1.0f / (e0 + e1);
        out[t * 2 + 0] = e0 * inv;
        out[t * 2 + 1] = e1 * inv;
    }
}

// -------------------------------- launch --------------------------------------
extern "C" void kernel_launch(void* const* d_in, const int* in_sizes, int n_in,
                              void* d_out, int out_size) {
    const int*   nf1   = (const int*)  d_in[0];
    const int*   nf2   = (const int*)  d_in[1];
    const float* emb1  = (const float*)d_in[2];
    const float* emb2  = (const float*)d_in[3];
    const float* Wiou1 = (const float*)d_in[4];
    const float* Wiou2 = (const float*)d_in[5];
    const float* Uiou1 = (const float*)d_in[6];
    const float* Uiou2 = (const float*)d_in[7];
    const float* UfW1  = (const float*)d_in[8];
    const float* Ufb1  = (const float*)d_in[9];
    const float* UfW2  = (const float*)d_in[10];
    const float* Ufb2  = (const float*)d_in[11];
    const float* biou1 = (const float*)d_in[12];
    const float* biou2 = (const float*)d_in[13];
    const float* Wf    = (const float*)d_in[14];
    const float* bf    = (const float*)d_in[15];
    float* out = (float*)d_out;

    float *P, *iouS, *h, *c, *cc, *ht, *UfT, *UiT, *WiT;
    cudaGetSymbolAddress((void**)&P,    g_P);
    cudaGetSymbolAddress((void**)&iouS, g_iou);
    cudaGetSymbolAddress((void**)&h,    g_h);
    cudaGetSymbolAddress((void**)&c,    g_c);
    cudaGetSymbolAddress((void**)&cc,   g_cc);
    cudaGetSymbolAddress((void**)&ht,   g_ht);
    cudaGetSymbolAddress((void**)&UfT,  g_UfT);
    cudaGetSymbolAddress((void**)&UiT,  g_UiT);
    cudaGetSymbolAddress((void**)&WiT,  g_WiT);

    const size_t Poff = (size_t)VOCAB * IOUW;
    const size_t Hoff = (size_t)NN * HID;
    const size_t Coff = (size_t)NLEAF * HID;
    const size_t Ioff = (size_t)NINT * IOUW;
    const size_t Toff = (size_t)NINT * HID;

    // 0) transpose weights to [N,K] row-major
    transpose_k<<<dim3(24, 8, 6), dim3(32, 8)>>>(
        TPair{UfW1, UfT, 256},            TPair{UfW2, UfT + 256*256, 256},
        TPair{Uiou1, UiT, 768},           TPair{Uiou2, UiT + 768*256, 768},
        TPair{Wiou1, WiT, 768},           TPair{Wiou2, WiT + 768*256, 768});

    // 1) token tables: P[b] = emb[b] @ W_iou[b]   [10000,256]@[256,768]
    {
        GemmArgs a0{emb1, WiT,            nullptr, nullptr, P,        VOCAB, IOUW, 0, 1, 0};
        GemmArgs a1{emb2, WiT + 768*256,  nullptr, nullptr, P + Poff, VOCAB, IOUW, 0, 1, 0};
        mma_gemm<0><<<dim3(IOUW/128, (VOCAB + 127)/128, 2), 256>>>(a0, a1);
    }
    // 2) fused leaf gather + activation -> h,c
    leaf_act_kernel<<<dim3(NLEAF, 1, 2), 256>>>(nf1, nf2, biou1, biou2);

    const int ps_[4]   = {21, 5, 1, 0};
    const int pcnt_[4] = {64, 16, 4, 1};
    const int cs_[4]   = {85, 21, 5, 1};
    const int ccnt_[4] = {256, 64, 16, 4};

    for (int L = 0; L < 4; L++) {
        int Mc = T_TREES * ccnt_[L];
        int Mp = T_TREES * pcnt_[L];
        // forget gate: cc = sigmoid(h_child @ Uf_W + Uf_b) * c_child
        {
            GemmArgs a0{h,        UfT,            Ufb1, c,        cc,        Mc, 256, cs_[L], ccnt_[L], 1};
            GemmArgs a1{h + Hoff, UfT + 256*256,  Ufb2, c + Hoff, cc + Coff, Mc, 256, cs_[L], ccnt_[L], 1};
            mma_gemm<1><<<dim3(2, (Mc + 127)/128, 2), 256>>>(a0, a1);
        }
        reduce_kernel<<<dim3(Mp, 1, 2), 256>>>(pcnt_[L], cs_[L], ccnt_[L]);
        // parent iou = h_tild @ U_iou
        {
            GemmArgs a0{ht,        UiT,            nullptr, nullptr, iouS,        Mp, IOUW, 0, 1, 0};
            GemmArgs a1{ht + Toff, UiT + 768*256,  nullptr, nullptr, iouS + Ioff, Mp, IOUW, 0, 1, 0};
            mma_gemm<0><<<dim3(IOUW/128, (Mp + 127)/128, 2), 256>>>(a0, a1);
        }
        act_kernel<<<dim3(Mp, 1, 2), 256>>>(biou1, biou2, ps_[L], pcnt_[L]);
    }

    readout_kernel<<<T_TREES, 256>>>(Wf, bf, out);
}

// round 6
// speedup vs baseline: 1.8676x; 1.0469x over previous
#include <cuda_runtime.h>
#include <math.h>
#include <stdint.h>

// ---------------- problem constants (structure is deterministic) ----------------
#define T_TREES   150
#define NPT       341          // nodes per tree (level-order, node0 = root)
#define NN        (T_TREES*NPT)
#define HID       256
#define IOUW      768
#define VOCAB     10000
#define LEAF_LOC0 85           // leaves are local nodes [85, 341)
#define LPT       256          // leaves per tree
#define NLEAF     (T_TREES*LPT)
#define NINT      (T_TREES*64) // max parents per level (9600)

// ---------------- scratch (device globals; no allocation allowed) ----------------
__device__ float g_P   [2u*VOCAB*IOUW];   // emb @ W_iou tables
__device__ float g_iou [2u*NINT*IOUW];    // iou scratch (internal nodes only)
__device__ float g_h   [2u*NN*HID];
__device__ float g_c   [2u*NN*HID];
__device__ float g_cc  [2u*NLEAF*HID];    // f * c_child per edge (compact child order)
__device__ float g_ht  [2u*NINT*HID];     // h_tild
__device__ float g_cs  [2u*NINT*HID];     // c_sum
__device__ float g_UfT [2u*256*256];      // Uf_W^T  [N=256,K=256] row-major
__device__ float g_UiT [2u*768*256];      // U_iou^T [N=768,K=256]
__device__ float g_WiT [2u*768*256];      // W_iou^T [N=768,K=256]

__device__ __forceinline__ float sigf(float x) { return 1.0f/(1.0f+__expf(-x)); }
__device__ __forceinline__ float tanh_fast(float x) {
    float y; asm("tanh.approx.f32 %0, %1;" : "=f"(y) : "f"(x)); return y;
}

// ---------------- tf32 mma.sync GEMM with cp.async double buffering --------------
// C[M,Ntot] = A[M,256] @ Bt[Ntot,256]^T
// BM=BN=128, BK=32, 256 threads = 8 warps (2 M x 4 N), warp tile 64x32.
struct GemmArgs {
    const float* A; const float* Bt; const float* bias; const float* Cst;
    float* Out; int M; int Ntot; int start; int rpt; int use_map;
};
__device__ __forceinline__ int rmap(const GemmArgs& a, int r) {
    return a.use_map ? ((r / a.rpt) * NPT + a.start + (r % a.rpt)) : r;
}
__device__ __forceinline__ unsigned smem_u32(const void* p) {
    unsigned a;
    asm("{ .reg .u64 t; cvta.to.shared.u64 t, %1; cvt.u32.u64 %0, t; }" : "=r"(a) : "l"(p));
    return a;
}
__device__ __forceinline__ void cp16(unsigned dst, const void* src, int bytes) {
    asm volatile("cp.async.ca.shared.global [%0], [%1], 16, %2;"
                 :: "r"(dst), "l"(src), "r"(bytes) : "memory");
}

#define SMS 36   // smem row stride (floats): conflict-free for mma fragment pattern
#define GEMM_SMEM (2u*2u*128u*SMS*4u)   // 2 stages x (A+B) x 128 x SMS floats

template<int EPI>   // 0: plain store ; 1: fgate: Out[r*256+c]=sig(acc+bias[c])*Cst[ridx*256+c]
__global__ __launch_bounds__(256, 2)
void mma_gemm(GemmArgs a0, GemmArgs a1) {
    GemmArgs a = (blockIdx.z == 0) ? a0 : a1;
    extern __shared__ float sm[];
    float* Asf = sm;                       // [2][128][SMS]
    float* Bsf = sm + 2 * 128 * SMS;       // [2][128][SMS]
    int tid = threadIdx.x, lane = tid & 31, wid = tid >> 5;
    int wm = wid >> 2, wn = wid & 3;
    int qr = lane >> 2, qc = lane & 3;
    int m0 = blockIdx.y * 128, n0 = blockIdx.x * 128;

    // loader: thread -> row tid>>1, k-half (tid&1)*16 ; 4 x 16B cp.async per tile
    int lrow = tid >> 1, lkh = (tid & 1) * 16;
    int gr = m0 + lrow;
    const float* Ap = a.A; int abytes = 0;
    if (gr < a.M) { Ap = a.A + (size_t)rmap(a, gr) * 256 + lkh; abytes = 16; }
    const float* Bp = a.Bt + (size_t)(n0 + lrow) * 256 + lkh;   // Ntot % 128 == 0
    unsigned dA0 = smem_u32(Asf) + (unsigned)(lrow * SMS + lkh) * 4u;
    unsigned dB0 = smem_u32(Bsf) + (unsigned)(lrow * SMS + lkh) * 4u;
    const unsigned stageB = 128u * SMS * 4u;

    float acc[4][4][4];
    #pragma unroll
    for (int mt = 0; mt < 4; mt++)
        #pragma unroll
        for (int nt = 0; nt < 4; nt++)
            #pragma unroll
            for (int i = 0; i < 4; i++) acc[mt][nt][i] = 0.f;

    // prologue: stage 0 <- chunk 0
    #pragma unroll
    for (int v = 0; v < 4; v++) {
        cp16(dA0 + v * 16, Ap + v * 4, abytes);
        cp16(dB0 + v * 16, Bp + v * 4, 16);
    }
    asm volatile("cp.async.commit_group;" ::: "memory");

    #pragma unroll
    for (int c = 0; c < 8; c++) {
        if (c < 7) {
            int st = (c + 1) & 1;
            int kc = (c + 1) * 32;
            #pragma unroll
            for (int v = 0; v < 4; v++) {
                cp16(dA0 + st * stageB + v * 16, Ap + kc + v * 4, abytes);
                cp16(dB0 + st * stageB + v * 16, Bp + kc + v * 4, 16);
            }
            asm volatile("cp.async.commit_group;" ::: "memory");
            asm volatile("cp.async.wait_group 1;" ::: "memory");
        } else {
            asm volatile("cp.async.wait_group 0;" ::: "memory");
        }
        __syncthreads();

        const unsigned* Asu = (const unsigned*)(Asf + (c & 1) * 128 * SMS);
        const unsigned* Bsu = (const unsigned*)(Bsf + (c & 1) * 128 * SMS);
        #pragma unroll
        for (int ks = 0; ks < 4; ks++) {
            int k0 = ks * 8;
            unsigned af[4][4], bf[4][2];
            #pragma unroll
            for (int mt = 0; mt < 4; mt++) {
                int ra = wm * 64 + mt * 16 + qr;
                af[mt][0] = Asu[(ra    ) * SMS + k0 + qc];
                af[mt][1] = Asu[(ra + 8) * SMS + k0 + qc];
                af[mt][2] = Asu[(ra    ) * SMS + k0 + qc + 4];
                af[mt][3] = Asu[(ra + 8) * SMS + k0 + qc + 4];
            }
            #pragma unroll
            for (int nt = 0; nt < 4; nt++) {
                int rb = wn * 32 + nt * 8 + qr;
                bf[nt][0] = Bsu[rb * SMS + k0 + qc];
                bf[nt][1] = Bsu[rb * SMS + k0 + qc + 4];
            }
            #pragma unroll
            for (int mt = 0; mt < 4; mt++)
                #pragma unroll
                for (int nt = 0; nt < 4; nt++) {
                    float* d = acc[mt][nt];
                    asm volatile(
                        "mma.sync.aligned.m16n8k8.row.col.f32.tf32.tf32.f32 "
                        "{%0,%1,%2,%3}, {%4,%5,%6,%7}, {%8,%9}, {%0,%1,%2,%3};"
                        : "+f"(d[0]), "+f"(d[1]), "+f"(d[2]), "+f"(d[3])
                        : "r"(af[mt][0]), "r"(af[mt][1]), "r"(af[mt][2]), "r"(af[mt][3]),
                          "r"(bf[nt][0]), "r"(bf[nt][1]));
                }
        }
        __syncthreads();
    }

    // epilogue: thread owns rows (qr, qr+8) of each m-tile, cols 2qc,2qc+1 per n-tile
    #pragma unroll
    for (int mt = 0; mt < 4; mt++) {
        #pragma unroll
        for (int half = 0; half < 2; half++) {
            int r = m0 + wm * 64 + mt * 16 + qr + half * 8;
            if (r >= a.M) continue;
            int ridx = rmap(a, r);
            #pragma unroll
            for (int nt = 0; nt < 4; nt++) {
                int col = n0 + wn * 32 + nt * 8 + qc * 2;
                float v0 = acc[mt][nt][half * 2 + 0];
                float v1 = acc[mt][nt][half * 2 + 1];
                if (EPI == 1) {
                    float b0 = __ldg(&a.bias[col]), b1 = __ldg(&a.bias[col + 1]);
                    const float* cst = a.Cst + (size_t)ridx * 256 + col;
                    float2 o;
                    o.x = sigf(v0 + b0) * cst[0];
                    o.y = sigf(v1 + b1) * cst[1];
                    *(float2*)(a.Out + (size_t)r * 256 + col) = o;
                } else {
                    *(float2*)(a.Out + (size_t)r * a.Ntot + col) = make_float2(v0, v1);
                }
            }
        }
    }
}

// ---------------- weight transpose: S[256,N] -> D[N,256] ------------------------
struct TPair { const float* s; float* d; int n; };
__global__ void transpose_k(TPair p0, TPair p1, TPair p2, TPair p3, TPair p4, TPair p5) {
    TPair p;
    switch (blockIdx.z) {
        case 0: p = p0; break; case 1: p = p1; break; case 2: p = p2; break;
        case 3: p = p3; break; case 4: p = p4; break; default: p = p5; break;
    }
    int x0 = blockIdx.x * 32;
    if (x0 >= p.n) return;
    int y0 = blockIdx.y * 32;
    __shared__ float t[32][33];
    #pragma unroll
    for (int s = 0; s < 32; s += 8)
        t[threadIdx.y + s][threadIdx.x] = p.s[(size_t)(y0 + threadIdx.y + s) * p.n + x0 + threadIdx.x];
    __syncthreads();
    #pragma unroll
    for (int s = 0; s < 32; s += 8)
        p.d[(size_t)(x0 + threadIdx.y + s) * 256 + y0 + threadIdx.x] = t[threadIdx.x][threadIdx.y + s];
}

// ------- fused leaf: iou = mean_s P[tok_s] cols (j,256+j,512+j) -> activation ----
__global__ void leaf_act_kernel(const int* __restrict__ nf1, const int* __restrict__ nf2,
                                const float* __restrict__ bi1, const float* __restrict__ bi2) {
    int b = blockIdx.z;
    const int* nf = b ? nf2 : nf1;
    const float* bias = b ? bi2 : bi1;
    int leaf = blockIdx.x;
    int tree = leaf >> 8, ll = leaf & 255;
    int gnode = tree * NPT + LEAF_LOC0 + ll;
    __shared__ int toks[8];
    if (threadIdx.x < 8) toks[threadIdx.x] = nf[gnode * 8 + threadIdx.x];
    __syncthreads();
    const float* P = g_P + (size_t)b * VOCAB * IOUW;
    int j = threadIdx.x;
    float si = 0.f, so = 0.f, su = 0.f;
    #pragma unroll
    for (int t = 0; t < 8; t++) {
        const float* row = P + (size_t)toks[t] * IOUW;
        si += __ldg(row + j);
        so += __ldg(row + 256 + j);
        su += __ldg(row + 512 + j);
    }
    float iv = si * 0.125f + bias[j];
    float ov = so * 0.125f + bias[256 + j];
    float uv = su * 0.125f + bias[512 + j];
    float c = sigf(iv) * tanh_fast(uv);
    float h = sigf(ov) * tanh_fast(c);
    g_h[(size_t)b * NN * HID + (size_t)gnode * HID + j] = h;
    g_c[(size_t)b * NN * HID + (size_t)gnode * HID + j] = c;
}

// ------------- activation for internal nodes (reads g_iou + g_cs) ---------------
__global__ void act_kernel(const float* __restrict__ bi1, const float* __restrict__ bi2,
                           int start, int rpt) {
    int b = blockIdx.z;
    const float* bias = b ? bi2 : bi1;
    int r = blockIdx.x, j = threadIdx.x;
    const float* iou = g_iou + (size_t)b * NINT * IOUW + (size_t)r * IOUW;
    float iv = iou[j]       + bias[j];
    float ov = iou[256 + j] + bias[256 + j];
    float uv = iou[512 + j] + bias[512 + j];
    float cs = g_cs[(size_t)b * NINT * HID + (size_t)r * HID + j];
    float c = sigf(iv) * tanh_fast(uv) + cs;
    float h = sigf(ov) * tanh_fast(c);
    int g = (r / rpt) * NPT + start + (r % rpt);
    g_h[(size_t)b * NN * HID + (size_t)g * HID + j] = h;
    g_c[(size_t)b * NN * HID + (size_t)g * HID + j] = c;
}

// ------------- 4-child reduction: h_tild = sum h_child, c_sum = sum f*c --------
__global__ void reduce_kernel(int pcnt, int cstart, int ccnt) {
    int b = blockIdx.z, p = blockIdx.x, j = threadIdx.x;
    int tree = p / pcnt, lp = p % pcnt;
    size_t hb = (size_t)b * NN * HID + ((size_t)(tree * NPT + cstart + 4 * lp)) * HID + j;
    size_t cb = (size_t)b * NLEAF * HID + ((size_t)(tree * ccnt + 4 * lp)) * HID + j;
    float hs = 0.f, cs = 0.f;
    #pragma unroll
    for (int k = 0; k < 4; k++) { hs += g_h[hb + (size_t)k * HID]; cs += g_cc[cb + (size_t)k * HID]; }
    g_ht[(size_t)b * NINT * HID + (size_t)p * HID + j] = hs;
    g_cs[(size_t)b * NINT * HID + (size_t)p * HID + j] = cs;
}

// ------------- readout: mean-h per tree, relu, concat @ Wf, leaky, softmax -----
__global__ void readout_kernel(const float* __restrict__ Wf, const float* __restrict__ bf,
                               float* __restrict__ out) {
    int t = blockIdx.x, j = threadIdx.x;
    float s1 = 0.f, s2 = 0.f;
    size_t base = (size_t)t * NPT * HID + j;
    for (int n = 0; n < NPT; n++) {
        s1 += g_h[base + (size_t)n * HID];
        s2 += g_h[(size_t)NN * HID + base + (size_t)n * HID];
    }
    float m1 = fmaxf(s1 * (1.0f / NPT), 0.f);
    float m2 = fmaxf(s2 * (1.0f / NPT), 0.f);
    float p0 = m1 * Wf[j * 2 + 0] + m2 * Wf[(256 + j) * 2 + 0];
    float p1 = m1 * Wf[j * 2 + 1] + m2 * Wf[(256 + j) * 2 + 1];
    __shared__ float sm0[256], sm1[256];
    sm0[j] = p0; sm1[j] = p1; __syncthreads();
    for (int s = 128; s > 0; s >>= 1) {
        if (j < s) { sm0[j] += sm0[j + s]; sm1[j] += sm1[j + s]; }
        __syncthreads();
    }
    if (j == 0) {
        float l0 = sm0[0] + bf[0], l1 = sm1[0] + bf[1];
        l0 = (l0 >= 0.f) ? l0 : 0.01f * l0;
        l1 = (l1 >= 0.f) ? l1 : 0.01f * l1;
        float mx = fmaxf(l0, l1);
        float e0 = __expf(l0 - mx), e1 = __expf(l1 - mx);
        float inv = 1.0f / (e0 + e1);
        out[t * 2 + 0] = e0 * inv;
        out[t * 2 + 1] = e1 * inv;
    }
}

// -------------------------------- launch --------------------------------------
extern "C" void kernel_launch(void* const* d_in, const int* in_sizes, int n_in,
                              void* d_out, int out_size) {
    const int*   nf1   = (const int*)  d_in[0];
    const int*   nf2   = (const int*)  d_in[1];
    const float* emb1  = (const float*)d_in[2];
    const float* emb2  = (const float*)d_in[3];
    const float* Wiou1 = (const float*)d_in[4];
    const float* Wiou2 = (const float*)d_in[5];
    const float* Uiou1 = (const float*)d_in[6];
    const float* Uiou2 = (const float*)d_in[7];
    const float* UfW1  = (const float*)d_in[8];
    const float* Ufb1  = (const float*)d_in[9];
    const float* UfW2  = (const float*)d_in[10];
    const float* Ufb2  = (const float*)d_in[11];
    const float* biou1 = (const float*)d_in[12];
    const float* biou2 = (const float*)d_in[13];
    const float* Wf    = (const float*)d_in[14];
    const float* bf    = (const float*)d_in[15];
    float* out = (float*)d_out;

    float *P, *iouS, *h, *c, *cc, *ht, *UfT, *UiT, *WiT;
    cudaGetSymbolAddress((void**)&P,    g_P);
    cudaGetSymbolAddress((void**)&iouS, g_iou);
    cudaGetSymbolAddress((void**)&h,    g_h);
    cudaGetSymbolAddress((void**)&c,    g_c);
    cudaGetSymbolAddress((void**)&cc,   g_cc);
    cudaGetSymbolAddress((void**)&ht,   g_ht);
    cudaGetSymbolAddress((void**)&UfT,  g_UfT);
    cudaGetSymbolAddress((void**)&UiT,  g_UiT);
    cudaGetSymbolAddress((void**)&WiT,  g_WiT);

    cudaFuncSetAttribute(mma_gemm<0>, cudaFuncAttributeMaxDynamicSharedMemorySize, GEMM_SMEM);
    cudaFuncSetAttribute(mma_gemm<1>, cudaFuncAttributeMaxDynamicSharedMemorySize, GEMM_SMEM);

    const size_t Poff = (size_t)VOCAB * IOUW;
    const size_t Hoff = (size_t)NN * HID;
    const size_t Coff = (size_t)NLEAF * HID;
    const size_t Ioff = (size_t)NINT * IOUW;
    const size_t Toff = (size_t)NINT * HID;

    // 0) transpose weights to [N,K] row-major
    transpose_k<<<dim3(24, 8, 6), dim3(32, 8)>>>(
        TPair{UfW1, UfT, 256},            TPair{UfW2, UfT + 256*256, 256},
        TPair{Uiou1, UiT, 768},           TPair{Uiou2, UiT + 768*256, 768},
        TPair{Wiou1, WiT, 768},           TPair{Wiou2, WiT + 768*256, 768});

    // 1) token tables: P[b] = emb[b] @ W_iou[b]   [10000,256]@[256,768]
    {
        GemmArgs a0{emb1, WiT,            nullptr, nullptr, P,        VOCAB, IOUW, 0, 1, 0};
        GemmArgs a1{emb2, WiT + 768*256,  nullptr, nullptr, P + Poff, VOCAB, IOUW, 0, 1, 0};
        mma_gemm<0><<<dim3(IOUW/128, (VOCAB + 127)/128, 2), 256, GEMM_SMEM>>>(a0, a1);
    }
    // 2) fused leaf gather + activation -> h,c
    leaf_act_kernel<<<dim3(NLEAF, 1, 2), 256>>>(nf1, nf2, biou1, biou2);

    const int ps_[4]   = {21, 5, 1, 0};
    const int pcnt_[4] = {64, 16, 4, 1};
    const int cs_[4]   = {85, 21, 5, 1};
    const int ccnt_[4] = {256, 64, 16, 4};

    for (int L = 0; L < 4; L++) {
        int Mc = T_TREES * ccnt_[L];
        int Mp = T_TREES * pcnt_[L];
        // forget gate: cc = sigmoid(h_child @ Uf_W + Uf_b) * c_child
        {
            GemmArgs a0{h,        UfT,            Ufb1, c,        cc,        Mc, 256, cs_[L], ccnt_[L], 1};
            GemmArgs a1{h + Hoff, UfT + 256*256,  Ufb2, c + Hoff, cc + Coff, Mc, 256, cs_[L], ccnt_[L], 1};
            mma_gemm<1><<<dim3(2, (Mc + 127)/128, 2), 256, GEMM_SMEM>>>(a0, a1);
        }
        reduce_kernel<<<dim3(Mp, 1, 2), 256>>>(pcnt_[L], cs_[L], ccnt_[L]);
        // parent iou = h_tild @ U_iou
        {
            GemmArgs a0{ht,        UiT,            nullptr, nullptr, iouS,        Mp, IOUW, 0, 1, 0};
            GemmArgs a1{ht + Toff, UiT + 768*256,  nullptr, nullptr, iouS + Ioff, Mp, IOUW, 0, 1, 0};
            mma_gemm<0><<<dim3(IOUW/128, (Mp + 127)/128, 2), 256, GEMM_SMEM>>>(a0, a1);
        }
        act_kernel<<<dim3(Mp, 1, 2), 256>>>(biou1, biou2, ps_[L], pcnt_[L]);
    }

    readout_kernel<<<T_TREES, 256>>>(Wf, bf, out);
}

// round 8
// speedup vs baseline: 2.4578x; 1.3160x over previous
#include <cuda_runtime.h>
#include <cuda_bf16.h>
#include <math.h>
#include <stdint.h>

// ---------------- problem constants (structure is deterministic) ----------------
#define T_TREES   150
#define NPT       341          // nodes per tree (level-order, node0 = root)
#define NN        (T_TREES*NPT)
#define HID       256
#define IOUW      768
#define VOCAB     10000
#define LEAF_LOC0 85           // leaves are local nodes [85, 341)
#define LPT       256          // leaves per tree
#define NLEAF     (T_TREES*LPT)
#define NINT      (T_TREES*64) // max parents per level (9600)

typedef __nv_bfloat16 bf16;

// ---------------- scratch (device globals; no allocation allowed) ----------------
__device__ float g_P   [2u*VOCAB*IOUW];   // emb @ W_iou tables (fp32)
__device__ float g_iou [2u*NINT*IOUW];    // iou scratch (internal nodes only)
__device__ float g_c   [2u*NN*HID];
__device__ float g_cc  [2u*NLEAF*HID];    // f * c_child per edge
__device__ float g_cs  [2u*NINT*HID];     // c_sum
__device__ bf16  g_hb  [2u*NN*HID];       // h (bf16, GEMM A operand)
__device__ bf16  g_htb [2u*NINT*HID];     // h_tild (bf16)
__device__ bf16  g_embB[2u*VOCAB*256];    // emb converted to bf16
__device__ bf16  g_UfTb[2u*256*256];      // Uf_W^T  [N=256,K=256] bf16
__device__ bf16  g_UiTb[2u*768*256];      // U_iou^T [N=768,K=256] bf16
__device__ bf16  g_WiTb[2u*768*256];      // W_iou^T [N=768,K=256] bf16

__device__ __forceinline__ float sigf(float x) { return 1.0f/(1.0f+__expf(-x)); }
__device__ __forceinline__ float tanh_fast(float x) {
    float y; asm("tanh.approx.f32 %0, %1;" : "=f"(y) : "f"(x)); return y;
}
__device__ __forceinline__ unsigned smem_u32(const void* p) {
    unsigned a;
    asm("{ .reg .u64 t; cvta.to.shared.u64 t, %1; cvt.u32.u64 %0, t; }" : "=r"(a) : "l"(p));
    return a;
}
__device__ __forceinline__ void cp16(unsigned dst, const void* src, int bytes) {
    asm volatile("cp.async.ca.shared.global [%0], [%1], 16, %2;"
                 :: "r"(dst), "l"(src), "r"(bytes) : "memory");
}
#define LDSM4(r0,r1,r2,r3,addr) \
    asm volatile("ldmatrix.sync.aligned.m8n8.x4.shared.b16 {%0,%1,%2,%3}, [%4];" \
        : "=r"(r0),"=r"(r1),"=r"(r2),"=r"(r3) : "r"(addr))

// ---------------- bf16 mma GEMM: C[M,Ntot] = A[M,256] @ Bt[Ntot,256]^T -----------
// BM=BN=128, BK=32, 256 threads = 8 warps (2 M x 4 N), warp tile 64x32.
struct GemmArgs {
    const bf16* A; const bf16* Bt; const float* bias; const float* Cst;
    float* Out; int M; int Ntot; int start; int rpt; int use_map;
};
__device__ __forceinline__ int rmap(const GemmArgs& a, int r) {
    return a.use_map ? ((r / a.rpt) * NPT + a.start + (r % a.rpt)) : r;
}

#define STRB 80u   // smem row stride bytes (40 bf16): conflict-free for ldmatrix

template<int EPI>   // 0: plain store ; 1: fgate: Out[r*256+c]=sig(acc+bias[c])*Cst[ridx*256+c]
__global__ __launch_bounds__(256, 2)
void mma_gemm(GemmArgs a0, GemmArgs a1) {
    GemmArgs a = (blockIdx.z == 0) ? a0 : a1;
    __shared__ __align__(16) char As[2][128 * STRB];
    __shared__ __align__(16) char Bs[2][128 * STRB];
    int tid = threadIdx.x, lane = tid & 31, wid = tid >> 5;
    int wm = wid >> 2, wn = wid & 3;
    int qr = lane >> 2, qc = lane & 3;
    int m0 = blockIdx.y * 128, n0 = blockIdx.x * 128;

    // loader: thread -> row tid>>1, half (tid&1)*16 bf16 (32B = 2 x cp16)
    int lrow = tid >> 1, lhalf = tid & 1;
    int gr = m0 + lrow;
    const bf16* Ap = a.A; int abytes = 0;
    if (gr < a.M) { Ap = a.A + (size_t)rmap(a, gr) * 256 + lhalf * 16; abytes = 16; }
    const bf16* Bp = a.Bt + (size_t)(n0 + lrow) * 256 + lhalf * 16;   // Ntot % 128 == 0
    unsigned dAl = smem_u32(As) + lrow * STRB + lhalf * 32u;
    unsigned dBl = smem_u32(Bs) + lrow * STRB + lhalf * 32u;
    const unsigned stageB = 128u * STRB;

    // ldmatrix per-lane offsets
    unsigned aRowOff = (((lane >> 3) & 1) * 8 + (lane & 7)) * STRB + (lane >> 4) * 16u;
    unsigned bRowOff = (((lane >> 4) << 3) + (lane & 7)) * STRB + ((lane >> 3) & 1) * 16u;
    unsigned aBase = smem_u32(As) + (wm * 64) * STRB + aRowOff;
    unsigned bBase = smem_u32(Bs) + (wn * 32) * STRB + bRowOff;

    float acc[4][4][4];
    #pragma unroll
    for (int mt = 0; mt < 4; mt++)
        #pragma unroll
        for (int nt = 0; nt < 4; nt++)
            #pragma unroll
            for (int i = 0; i < 4; i++) acc[mt][nt][i] = 0.f;

    // prologue: stage 0 <- chunk 0 (32 bf16 = 64B per row)
    cp16(dAl,      Ap,     abytes);
    cp16(dAl + 16, Ap + 8, abytes);
    cp16(dBl,      Bp,     16);
    cp16(dBl + 16, Bp + 8, 16);
    asm volatile("cp.async.commit_group;" ::: "memory");

    #pragma unroll
    for (int c = 0; c < 8; c++) {
        if (c < 7) {
            unsigned st = (c + 1) & 1;
            int kc = (c + 1) * 32;
            cp16(dAl + st * stageB,      Ap + kc,     abytes);
            cp16(dAl + st * stageB + 16, Ap + kc + 8, abytes);
            cp16(dBl + st * stageB,      Bp + kc,     16);
            cp16(dBl + st * stageB + 16, Bp + kc + 8, 16);
            asm volatile("cp.async.commit_group;" ::: "memory");
            asm volatile("cp.async.wait_group 1;" ::: "memory");
        } else {
            asm volatile("cp.async.wait_group 0;" ::: "memory");
        }
        __syncthreads();

        unsigned aS = aBase + (c & 1) * stageB;
        unsigned bS = bBase + (c & 1) * stageB;
        #pragma unroll
        for (int ks = 0; ks < 2; ks++) {        // two k16 steps per 32-chunk
            unsigned koff = ks * 32u;           // 16 bf16 = 32B
            unsigned af[4][4], bfr[4][2];
            #pragma unroll
            for (int mt = 0; mt < 4; mt++)
                LDSM4(af[mt][0], af[mt][1], af[mt][2], af[mt][3],
                      aS + mt * 16u * STRB + koff);
            LDSM4(bfr[0][0], bfr[0][1], bfr[1][0], bfr[1][1], bS + koff);
            LDSM4(bfr[2][0], bfr[2][1], bfr[3][0], bfr[3][1], bS + 16u * STRB + koff);
            #pragma unroll
            for (int mt = 0; mt < 4; mt++)
                #pragma unroll
                for (int nt = 0; nt < 4; nt++) {
                    float* d = acc[mt][nt];
                    asm volatile(
                        "mma.sync.aligned.m16n8k16.row.col.f32.bf16.bf16.f32 "
                        "{%0,%1,%2,%3}, {%4,%5,%6,%7}, {%8,%9}, {%0,%1,%2,%3};"
                        : "+f"(d[0]), "+f"(d[1]), "+f"(d[2]), "+f"(d[3])
                        : "r"(af[mt][0]), "r"(af[mt][1]), "r"(af[mt][2]), "r"(af[mt][3]),
                          "r"(bfr[nt][0]), "r"(bfr[nt][1]));
                }
        }
        __syncthreads();
    }

    // epilogue: thread owns rows (qr, qr+8) of each m-tile, cols 2qc,2qc+1 per n-tile
    #pragma unroll
    for (int mt = 0; mt < 4; mt++) {
        #pragma unroll
        for (int half = 0; half < 2; half++) {
            int r = m0 + wm * 64 + mt * 16 + qr + half * 8;
            if (r >= a.M) continue;
            int ridx = rmap(a, r);
            #pragma unroll
            for (int nt = 0; nt < 4; nt++) {
                int col = n0 + wn * 32 + nt * 8 + qc * 2;
                float v0 = acc[mt][nt][half * 2 + 0];
                float v1 = acc[mt][nt][half * 2 + 1];
                if (EPI == 1) {
                    float b0 = __ldg(&a.bias[col]), b1 = __ldg(&a.bias[col + 1]);
                    const float* cst = a.Cst + (size_t)ridx * 256 + col;
                    float2 o;
                    o.x = sigf(v0 + b0) * cst[0];
                    o.y = sigf(v1 + b1) * cst[1];
                    *(float2*)(a.Out + (size_t)r * 256 + col) = o;
                } else {
                    *(float2*)(a.Out + (size_t)r * a.Ntot + col) = make_float2(v0, v1);
                }
            }
        }
    }
}

// ---------------- weight transpose: S[256,N] fp32 -> D[N,256] bf16 ---------------
struct TPair { const float* s; bf16* d; int n; };
__global__ void transpose_k(TPair p0, TPair p1, TPair p2, TPair p3, TPair p4, TPair p5) {
    TPair p;
    switch (blockIdx.z) {
        case 0: p = p0; break; case 1: p = p1; break; case 2: p = p2; break;
        case 3: p = p3; break; case 4: p = p4; break; default: p = p5; break;
    }
    int x0 = blockIdx.x * 32;
    if (x0 >= p.n) return;
    int y0 = blockIdx.y * 32;
    __shared__ float t[32][33];
    #pragma unroll
    for (int s = 0; s < 32; s += 8)
        t[threadIdx.y + s][threadIdx.x] = p.s[(size_t)(y0 + threadIdx.y + s) * p.n + x0 + threadIdx.x];
    __syncthreads();
    #pragma unroll
    for (int s = 0; s < 32; s += 8)
        p.d[(size_t)(x0 + threadIdx.y + s) * 256 + y0 + threadIdx.x] =
            __float2bfloat16(t[threadIdx.x][threadIdx.y + s]);
}

// ---------------- emb fp32 -> bf16 ----------------------------------------------
__global__ void conv_emb(const float* __restrict__ e1, const float* __restrict__ e2) {
    int i = blockIdx.x * 1024 + threadIdx.x;
    const unsigned n = VOCAB * 256u;
    if (i < (int)n) {
        g_embB[i]     = __float2bfloat16(e1[i]);
        g_embB[n + i] = __float2bfloat16(e2[i]);
    }
}

// ------- fused leaf: iou = mean_s P[tok_s] cols (j,256+j,512+j) -> activation ----
__global__ void leaf_act_kernel(const int* __restrict__ nf1, const int* __restrict__ nf2,
                                const float* __restrict__ bi1, const float* __restrict__ bi2) {
    int b = blockIdx.z;
    const int* nf = b ? nf2 : nf1;
    const float* bias = b ? bi2 : bi1;
    int leaf = blockIdx.x;
    int tree = leaf >> 8, ll = leaf & 255;
    int gnode = tree * NPT + LEAF_LOC0 + ll;
    __shared__ int toks[8];
    if (threadIdx.x < 8) toks[threadIdx.x] = nf[gnode * 8 + threadIdx.x];
    __syncthreads();
    const float* P = g_P + (size_t)b * VOCAB * IOUW;
    int j = threadIdx.x;
    float si = 0.f, so = 0.f, su = 0.f;
    #pragma unroll
    for (int t = 0; t < 8; t++) {
        const float* row = P + (size_t)toks[t] * IOUW;
        si += __ldg(row + j);
        so += __ldg(row + 256 + j);
        su += __ldg(row + 512 + j);
    }
    float iv = si * 0.125f + bias[j];
    float ov = so * 0.125f + bias[256 + j];
    float uv = su * 0.125f + bias[512 + j];
    float c = sigf(iv) * tanh_fast(uv);
    float h = sigf(ov) * tanh_fast(c);
    g_hb[(size_t)b * NN * HID + (size_t)gnode * HID + j] = __float2bfloat16(h);
    g_c [(size_t)b * NN * HID + (size_t)gnode * HID + j] = c;
}

// ------------- activation for internal nodes (reads g_iou + g_cs) ---------------
__global__ void act_kernel(const float* __restrict__ bi1, const float* __restrict__ bi2,
                           int start, int rpt) {
    int b = blockIdx.z;
    const float* bias = b ? bi2 : bi1;
    int r = blockIdx.x, j = threadIdx.x;
    const float* iou = g_iou + (size_t)b * NINT * IOUW + (size_t)r * IOUW;
    float iv = iou[j]       + bias[j];
    float ov = iou[256 + j] + bias[256 + j];
    float uv = iou[512 + j] + bias[512 + j];
    float cs = g_cs[(size_t)b * NINT * HID + (size_t)r * HID + j];
    float c = sigf(iv) * tanh_fast(uv) + cs;
    float h = sigf(ov) * tanh_fast(c);
    int g = (r / rpt) * NPT + start + (r % rpt);
    g_hb[(size_t)b * NN * HID + (size_t)g * HID + j] = __float2bfloat16(h);
    g_c [(size_t)b * NN * HID + (size_t)g * HID + j] = c;
}

// ------------- 4-child reduction: h_tild = sum h_child, c_sum = sum f*c --------
__global__ void reduce_kernel(int pcnt, int cstart, int ccnt) {
    int b = blockIdx.z, p = blockIdx.x, j = threadIdx.x;
    int tree = p / pcnt, lp = p % pcnt;
    size_t hb = (size_t)b * NN * HID + ((size_t)(tree * NPT + cstart + 4 * lp)) * HID + j;
    size_t cb = (size_t)b * NLEAF * HID + ((size_t)(tree * ccnt + 4 * lp)) * HID + j;
    float hs = 0.f, cs = 0.f;
    #pragma unroll
    for (int k = 0; k < 4; k++) {
        hs += __bfloat162float(g_hb[hb + (size_t)k * HID]);
        cs += g_cc[cb + (size_t)k * HID];
    }
    g_htb[(size_t)b * NINT * HID + (size_t)p * HID + j] = __float2bfloat16(hs);
    g_cs [(size_t)b * NINT * HID + (size_t)p * HID + j] = cs;
}

// ------------- readout: mean-h per tree, relu, concat @ Wf, leaky, softmax -----
__global__ void readout_kernel(const float* __restrict__ Wf, const float* __restrict__ bf,
                               float* __restrict__ out) {
    int t = blockIdx.x, j = threadIdx.x;
    float s1 = 0.f, s2 = 0.f;
    size_t base = (size_t)t * NPT * HID + j;
    for (int n = 0; n < NPT; n++) {
        s1 += __bfloat162float(g_hb[base + (size_t)n * HID]);
        s2 += __bfloat162float(g_hb[(size_t)NN * HID + base + (size_t)n * HID]);
    }
    float m1 = fmaxf(s1 * (1.0f / NPT), 0.f);
    float m2 = fmaxf(s2 * (1.0f / NPT), 0.f);
    float p0 = m1 * Wf[j * 2 + 0] + m2 * Wf[(256 + j) * 2 + 0];
    float p1 = m1 * Wf[j * 2 + 1] + m2 * Wf[(256 + j) * 2 + 1];
    __shared__ float sm0[256], sm1[256];
    sm0[j] = p0; sm1[j] = p1; __syncthreads();
    for (int s = 128; s > 0; s >>= 1) {
        if (j < s) { sm0[j] += sm0[j + s]; sm1[j] += sm1[j + s]; }
        __syncthreads();
    }
    if (j == 0) {
        float l0 = sm0[0] + bf[0], l1 = sm1[0] + bf[1];
        l0 = (l0 >= 0.f) ? l0 : 0.01f * l0;
        l1 = (l1 >= 0.f) ? l1 : 0.01f * l1;
        float mx = fmaxf(l0, l1);
        float e0 = __expf(l0 - mx), e1 = __expf(l1 - mx);
        float inv = 1.0f / (e0 + e1);
        out[t * 2 + 0] = e0 * inv;
        out[t * 2 + 1] = e1 * inv;
    }
}

// -------------------------------- launch --------------------------------------
extern "C" void kernel_launch(void* const* d_in, const int* in_sizes, int n_in,
                              void* d_out, int out_size) {
    const int*   nf1   = (const int*)  d_in[0];
    const int*   nf2   = (const int*)  d_in[1];
    const float* emb1  = (const float*)d_in[2];
    const float* emb2  = (const float*)d_in[3];
    const float* Wiou1 = (const float*)d_in[4];
    const float* Wiou2 = (const float*)d_in[5];
    const float* Uiou1 = (const float*)d_in[6];
    const float* Uiou2 = (const float*)d_in[7];
    const float* UfW1  = (const float*)d_in[8];
    const float* Ufb1  = (const float*)d_in[9];
    const float* UfW2  = (const float*)d_in[10];
    const float* Ufb2  = (const float*)d_in[11];
    const float* biou1 = (const float*)d_in[12];
    const float* biou2 = (const float*)d_in[13];
    const float* Wf    = (const float*)d_in[14];
    const float* bf    = (const float*)d_in[15];
    float* out = (float*)d_out;

    float *P, *iouS, *c, *cc;
    bf16 *hb, *htb, *embB, *UfTb, *UiTb, *WiTb;
    cudaGetSymbolAddress((void**)&P,    g_P);
    cudaGetSymbolAddress((void**)&iouS, g_iou);
    cudaGetSymbolAddress((void**)&c,    g_c);
    cudaGetSymbolAddress((void**)&cc,   g_cc);
    cudaGetSymbolAddress((void**)&hb,   g_hb);
    cudaGetSymbolAddress((void**)&htb,  g_htb);
    cudaGetSymbolAddress((void**)&embB, g_embB);
    cudaGetSymbolAddress((void**)&UfTb, g_UfTb);
    cudaGetSymbolAddress((void**)&UiTb, g_UiTb);
    cudaGetSymbolAddress((void**)&WiTb, g_WiTb);

    const size_t Poff = (size_t)VOCAB * IOUW;
    const size_t Hoff = (size_t)NN * HID;
    const size_t Coff = (size_t)NLEAF * HID;
    const size_t Ioff = (size_t)NINT * IOUW;
    const size_t Toff = (size_t)NINT * HID;

    // 0) weight transpose (fp32->bf16) + emb conversion
    transpose_k<<<dim3(24, 8, 6), dim3(32, 8)>>>(
        TPair{UfW1, UfTb, 256},           TPair{UfW2, UfTb + 256*256, 256},
        TPair{Uiou1, UiTb, 768},          TPair{Uiou2, UiTb + 768*256, 768},
        TPair{Wiou1, WiTb, 768},          TPair{Wiou2, WiTb + 768*256, 768});
    conv_emb<<<(VOCAB*256 + 1023)/1024, 1024>>>(emb1, emb2);

    // 1) token tables: P[b] = emb[b] @ W_iou[b]
    {
        GemmArgs a0{embB,              WiTb,           nullptr, nullptr, P,        VOCAB, IOUW, 0, 1, 0};
        GemmArgs a1{embB + VOCAB*256,  WiTb + 768*256, nullptr, nullptr, P + Poff, VOCAB, IOUW, 0, 1, 0};
        mma_gemm<0><<<dim3(IOUW/128, (VOCAB + 127)/128, 2), 256>>>(a0, a1);
    }
    // 2) fused leaf gather + activation -> h,c
    leaf_act_kernel<<<dim3(NLEAF, 1, 2), 256>>>(nf1, nf2, biou1, biou2);

    const int ps_[4]   = {21, 5, 1, 0};
    const int pcnt_[4] = {64, 16, 4, 1};
    const int cs_[4]   = {85, 21, 5, 1};
    const int ccnt_[4] = {256, 64, 16, 4};

    for (int L = 0; L < 4; L++) {
        int Mc = T_TREES * ccnt_[L];
        int Mp = T_TREES * pcnt_[L];
        // forget gate: cc = sigmoid(h_child @ Uf_W + Uf_b) * c_child
        {
            GemmArgs a0{hb,        UfTb,           Ufb1, c,        cc,        Mc, 256, cs_[L], ccnt_[L], 1};
            GemmArgs a1{hb + Hoff, UfTb + 256*256, Ufb2, c + Hoff, cc + Coff, Mc, 256, cs_[L], ccnt_[L], 1};
            mma_gemm<1><<<dim3(2, (Mc + 127)/128, 2), 256>>>(a0, a1);
        }
        reduce_kernel<<<dim3(Mp, 1, 2), 256>>>(pcnt_[L], cs_[L], ccnt_[L]);
        // parent iou = h_tild @ U_iou
        {
            GemmArgs a0{htb,        UiTb,           nullptr, nullptr, iouS,        Mp, IOUW, 0, 1, 0};
            GemmArgs a1{htb + Toff, UiTb + 768*256, nullptr, nullptr, iouS + Ioff, Mp, IOUW, 0, 1, 0};
            mma_gemm<0><<<dim3(IOUW/128, (Mp + 127)/128, 2), 256>>>(a0, a1);
        }
        act_kernel<<<dim3(Mp, 1, 2), 256>>>(biou1, biou2, ps_[L], pcnt_[L]);
    }

    readout_kernel<<<T_TREES, 256>>>(Wf, bf, out);
}

// round 9
// speedup vs baseline: 2.5689x; 1.0452x over previous
#include <cuda_runtime.h>
#include <cuda_bf16.h>
#include <math.h>
#include <stdint.h>

// ---------------- problem constants (structure is deterministic) ----------------
#define T_TREES   150
#define NPT       341          // nodes per tree (level-order, node0 = root)
#define NN        (T_TREES*NPT)
#define HID       256
#define IOUW      768
#define VOCAB     10000
#define LEAF_LOC0 85           // leaves are local nodes [85, 341)
#define LPT       256          // leaves per tree
#define NLEAF     (T_TREES*LPT)
#define NINT      (T_TREES*64) // max parents per level (9600)

typedef __nv_bfloat16 bf16;

// ---------------- scratch (device globals; no allocation allowed) ----------------
__device__ bf16  g_Pb  [2u*VOCAB*IOUW];   // emb @ W_iou tables (bf16, L2-resident)
__device__ float g_iou [2u*NINT*IOUW];    // iou scratch (internal nodes only)
__device__ float g_c   [2u*NN*HID];
__device__ float g_cc  [2u*NLEAF*HID];    // f * c_child per edge (compact child order)
__device__ bf16  g_hb  [2u*NN*HID];       // h (bf16, GEMM A operand)
__device__ bf16  g_embB[2u*VOCAB*256];    // emb converted to bf16
__device__ bf16  g_UfTb[2u*256*256];      // Uf_W^T  [N=256,K=256] bf16
__device__ bf16  g_UiTb[2u*768*256];      // U_iou^T [N=768,K=256] bf16
__device__ bf16  g_WiTb[2u*768*256];      // W_iou^T [N=768,K=256] bf16

__device__ __forceinline__ float sigf(float x) { return 1.0f/(1.0f+__expf(-x)); }
__device__ __forceinline__ float tanh_fast(float x) {
    float y; asm("tanh.approx.f32 %0, %1;" : "=f"(y) : "f"(x)); return y;
}
__device__ __forceinline__ unsigned smem_u32(const void* p) {
    unsigned a;
    asm("{ .reg .u64 t; cvta.to.shared.u64 t, %1; cvt.u32.u64 %0, t; }" : "=r"(a) : "l"(p));
    return a;
}
__device__ __forceinline__ void cp16(unsigned dst, const void* src, int bytes) {
    asm volatile("cp.async.ca.shared.global [%0], [%1], 16, %2;"
                 :: "r"(dst), "l"(src), "r"(bytes) : "memory");
}
#define LDSM4(r0,r1,r2,r3,addr) \
    asm volatile("ldmatrix.sync.aligned.m8n8.x4.shared.b16 {%0,%1,%2,%3}, [%4];" \
        : "=r"(r0),"=r"(r1),"=r"(r2),"=r"(r3) : "r"(addr))

__device__ __forceinline__ unsigned addb2(unsigned x, unsigned y) {
    __nv_bfloat162 a = *(__nv_bfloat162*)&x, b = *(__nv_bfloat162*)&y;
    __nv_bfloat162 r = __hadd2(a, b);
    return *(unsigned*)&r;
}
// sum 4 consecutive bf16 rows (stride 256) at 16B granularity
__device__ __forceinline__ uint4 bsum4(const bf16* p) {
    uint4 a = *(const uint4*)p, b = *(const uint4*)(p + 256);
    uint4 c = *(const uint4*)(p + 512), d = *(const uint4*)(p + 768);
    uint4 r;
    r.x = addb2(addb2(a.x, b.x), addb2(c.x, d.x));
    r.y = addb2(addb2(a.y, b.y), addb2(c.y, d.y));
    r.z = addb2(addb2(a.z, b.z), addb2(c.z, d.z));
    r.w = addb2(addb2(a.w, b.w), addb2(c.w, d.w));
    return r;
}

// ---------------- bf16 mma GEMM: C[M,Ntot] = A[M,256] @ Bt[Ntot,256]^T -----------
// BM=BN=128, BK=32, 256 threads = 8 warps (2 M x 4 N), warp tile 64x32.
// mode: 0 direct rows; 1 node-mapped rows; 2 on-the-fly 4-child-row sum
struct GemmArgs {
    const bf16* A; const bf16* Bt; const float* bias; const float* Cst;
    void* Out; int M; int Ntot; int start; int rpt; int mode;
};
__device__ __forceinline__ int rmap(const GemmArgs& a, int r) {
    return (a.mode == 1) ? ((r / a.rpt) * NPT + a.start + (r % a.rpt)) : r;
}

#define STRB 80u   // smem row stride bytes (40 bf16): conflict-free for ldmatrix

template<int EPI>   // 0: fp32 store ; 1: fgate sig(acc+bias)*Cst -> fp32 ; 2: bf16 store
__global__ __launch_bounds__(256, 2)
void mma_gemm(GemmArgs a0, GemmArgs a1) {
    GemmArgs a = (blockIdx.z == 0) ? a0 : a1;
    __shared__ __align__(16) char As[2][128 * STRB];
    __shared__ __align__(16) char Bs[2][128 * STRB];
    int tid = threadIdx.x, lane = tid & 31, wid = tid >> 5;
    int wm = wid >> 2, wn = wid & 3;
    int qr = lane >> 2, qc = lane & 3;
    int m0 = blockIdx.y * 128, n0 = blockIdx.x * 128;

    // loader: thread -> row tid>>1, half (tid&1)*16 bf16 (32B)
    int lrow = tid >> 1, lhalf = tid & 1;
    int gr = m0 + lrow;
    const bf16* Ap = nullptr;
    if (gr < a.M) {
        if (a.mode == 2)
            Ap = a.A + (size_t)((gr / a.rpt) * NPT + a.start + 4 * (gr % a.rpt)) * 256 + lhalf * 16;
        else
            Ap = a.A + (size_t)rmap(a, gr) * 256 + lhalf * 16;
    }
    const bf16* ApSafe = Ap ? Ap : a.A;
    int abytes = Ap ? 16 : 0;
    const bf16* Bp = a.Bt + (size_t)(n0 + lrow) * 256 + lhalf * 16;   // Ntot % 128 == 0
    unsigned dAl = smem_u32(As) + lrow * STRB + lhalf * 32u;
    unsigned dBl = smem_u32(Bs) + lrow * STRB + lhalf * 32u;
    const unsigned stageB = 128u * STRB;

    // ldmatrix per-lane offsets
    unsigned aRowOff = (((lane >> 3) & 1) * 8 + (lane & 7)) * STRB + (lane >> 4) * 16u;
    unsigned bRowOff = (((lane >> 4) << 3) + (lane & 7)) * STRB + ((lane >> 3) & 1) * 16u;
    unsigned aBase = smem_u32(As) + (wm * 64) * STRB + aRowOff;
    unsigned bBase = smem_u32(Bs) + (wn * 32) * STRB + bRowOff;

    float acc[4][4][4];
    #pragma unroll
    for (int mt = 0; mt < 4; mt++)
        #pragma unroll
        for (int nt = 0; nt < 4; nt++)
            #pragma unroll
            for (int i = 0; i < 4; i++) acc[mt][nt][i] = 0.f;

    // prologue: stage 0 <- chunk 0
    if (a.mode == 2) {
        uint4 z = make_uint4(0,0,0,0);
        uint4 s0 = Ap ? bsum4(Ap)     : z;
        uint4 s1 = Ap ? bsum4(Ap + 8) : z;
        *(uint4*)(&As[0][lrow * STRB + lhalf * 32u])      = s0;
        *(uint4*)(&As[0][lrow * STRB + lhalf * 32u + 16]) = s1;
    } else {
        cp16(dAl,      ApSafe,     abytes);
        cp16(dAl + 16, ApSafe + 8, abytes);
    }
    cp16(dBl,      Bp,     16);
    cp16(dBl + 16, Bp + 8, 16);
    asm volatile("cp.async.commit_group;" ::: "memory");

    #pragma unroll
    for (int c = 0; c < 8; c++) {
        if (c < 7) {
            unsigned st = (c + 1) & 1;
            int kc = (c + 1) * 32;
            if (a.mode == 2) {
                uint4 z = make_uint4(0,0,0,0);
                uint4 s0 = Ap ? bsum4(Ap + kc)     : z;
                uint4 s1 = Ap ? bsum4(Ap + kc + 8) : z;
                *(uint4*)(&As[st][lrow * STRB + lhalf * 32u])      = s0;
                *(uint4*)(&As[st][lrow * STRB + lhalf * 32u + 16]) = s1;
            } else {
                cp16(dAl + st * stageB,      ApSafe + kc,     abytes);
                cp16(dAl + st * stageB + 16, ApSafe + kc + 8, abytes);
            }
            cp16(dBl + st * stageB,      Bp + kc,     16);
            cp16(dBl + st * stageB + 16, Bp + kc + 8, 16);
            asm volatile("cp.async.commit_group;" ::: "memory");
            asm volatile("cp.async.wait_group 1;" ::: "memory");
        } else {
            asm volatile("cp.async.wait_group 0;" ::: "memory");
        }
        __syncthreads();

        unsigned aS = aBase + (c & 1) * stageB;
        unsigned bS = bBase + (c & 1) * stageB;
        #pragma unroll
        for (int ks = 0; ks < 2; ks++) {        // two k16 steps per 32-chunk
            unsigned koff = ks * 32u;           // 16 bf16 = 32B
            unsigned af[4][4], bfr[4][2];
            #pragma unroll
            for (int mt = 0; mt < 4; mt++)
                LDSM4(af[mt][0], af[mt][1], af[mt][2], af[mt][3],
                      aS + mt * 16u * STRB + koff);
            LDSM4(bfr[0][0], bfr[0][1], bfr[1][0], bfr[1][1], bS + koff);
            LDSM4(bfr[2][0], bfr[2][1], bfr[3][0], bfr[3][1], bS + 16u * STRB + koff);
            #pragma unroll
            for (int mt = 0; mt < 4; mt++)
                #pragma unroll
                for (int nt = 0; nt < 4; nt++) {
                    float* d = acc[mt][nt];
                    asm volatile(
                        "mma.sync.aligned.m16n8k16.row.col.f32.bf16.bf16.f32 "
                        "{%0,%1,%2,%3}, {%4,%5,%6,%7}, {%8,%9}, {%0,%1,%2,%3};"
                        : "+f"(d[0]), "+f"(d[1]), "+f"(d[2]), "+f"(d[3])
                        : "r"(af[mt][0]), "r"(af[mt][1]), "r"(af[mt][2]), "r"(af[mt][3]),
                          "r"(bfr[nt][0]), "r"(bfr[nt][1]));
                }
        }
        __syncthreads();
    }

    // epilogue: thread owns rows (qr, qr+8) of each m-tile, cols 2qc,2qc+1 per n-tile
    #pragma unroll
    for (int mt = 0; mt < 4; mt++) {
        #pragma unroll
        for (int half = 0; half < 2; half++) {
            int r = m0 + wm * 64 + mt * 16 + qr + half * 8;
            if (r >= a.M) continue;
            int ridx = rmap(a, r);
            #pragma unroll
            for (int nt = 0; nt < 4; nt++) {
                int col = n0 + wn * 32 + nt * 8 + qc * 2;
                float v0 = acc[mt][nt][half * 2 + 0];
                float v1 = acc[mt][nt][half * 2 + 1];
                if (EPI == 1) {
                    float b0 = __ldg(&a.bias[col]), b1 = __ldg(&a.bias[col + 1]);
                    const float* cst = a.Cst + (size_t)ridx * 256 + col;
                    float2 o;
                    o.x = sigf(v0 + b0) * cst[0];
                    o.y = sigf(v1 + b1) * cst[1];
                    *(float2*)((float*)a.Out + (size_t)r * 256 + col) = o;
                } else if (EPI == 2) {
                    __nv_bfloat162 o = __floats2bfloat162_rn(v0, v1);
                    *(__nv_bfloat162*)((bf16*)a.Out + (size_t)r * a.Ntot + col) = o;
                } else {
                    *(float2*)((float*)a.Out + (size_t)r * a.Ntot + col) = make_float2(v0, v1);
                }
            }
        }
    }
}

// ---------------- weight transpose: S[256,N] fp32 -> D[N,256] bf16 ---------------
struct TPair { const float* s; bf16* d; int n; };
__global__ void transpose_k(TPair p0, TPair p1, TPair p2, TPair p3, TPair p4, TPair p5) {
    TPair p;
    switch (blockIdx.z) {
        case 0: p = p0; break; case 1: p = p1; break; case 2: p = p2; break;
        case 3: p = p3; break; case 4: p = p4; break; default: p = p5; break;
    }
    int x0 = blockIdx.x * 32;
    if (x0 >= p.n) return;
    int y0 = blockIdx.y * 32;
    __shared__ float t[32][33];
    #pragma unroll
    for (int s = 0; s < 32; s += 8)
        t[threadIdx.y + s][threadIdx.x] = p.s[(size_t)(y0 + threadIdx.y + s) * p.n + x0 + threadIdx.x];
    __syncthreads();
    #pragma unroll
    for (int s = 0; s < 32; s += 8)
        p.d[(size_t)(x0 + threadIdx.y + s) * 256 + y0 + threadIdx.x] =
            __float2bfloat16(t[threadIdx.x][threadIdx.y + s]);
}

// ---------------- emb fp32 -> bf16 ----------------------------------------------
__global__ void conv_emb(const float* __restrict__ e1, const float* __restrict__ e2) {
    int i = blockIdx.x * 1024 + threadIdx.x;
    const unsigned n = VOCAB * 256u;
    if (i < (int)n) {
        g_embB[i]     = __float2bfloat16(e1[i]);
        g_embB[n + i] = __float2bfloat16(e2[i]);
    }
}

// ------- fused leaf: iou = mean_s P[tok_s] -> activation (bf16 table, u32 loads) --
__global__ __launch_bounds__(128)
void leaf_act_kernel(const int* __restrict__ nf1, const int* __restrict__ nf2,
                     const float* __restrict__ bi1, const float* __restrict__ bi2) {
    int b = blockIdx.z;
    const int* nf = b ? nf2 : nf1;
    const float* bias = b ? bi2 : bi1;
    int leaf = blockIdx.x;
    int tree = leaf >> 8, ll = leaf & 255;
    int gnode = tree * NPT + LEAF_LOC0 + ll;
    __shared__ int toks[8];
    if (threadIdx.x < 8) toks[threadIdx.x] = nf[gnode * 8 + threadIdx.x];
    __syncthreads();
    const unsigned* P = (const unsigned*)(g_Pb + (size_t)b * VOCAB * IOUW);  // 384 u32/row
    int t = threadIdx.x;   // cols 2t, 2t+1 of each 256-col segment
    float2 si = make_float2(0.f,0.f), so = si, su = si;
    #pragma unroll
    for (int s = 0; s < 8; s++) {
        const unsigned* row = P + (size_t)toks[s] * 384;
        unsigned ui = __ldg(row + t);
        unsigned uo = __ldg(row + 128 + t);
        unsigned uu = __ldg(row + 256 + t);
        float2 fi = __bfloat1622float2(*(__nv_bfloat162*)&ui);
        float2 fo = __bfloat1622float2(*(__nv_bfloat162*)&uo);
        float2 fu = __bfloat1622float2(*(__nv_bfloat162*)&uu);
        si.x += fi.x; si.y += fi.y;
        so.x += fo.x; so.y += fo.y;
        su.x += fu.x; su.y += fu.y;
    }
    float2 bi = *(const float2*)&bias[2*t];
    float2 bo = *(const float2*)&bias[256 + 2*t];
    float2 bu = *(const float2*)&bias[512 + 2*t];
    float c0 = sigf(si.x*0.125f + bi.x) * tanh_fast(su.x*0.125f + bu.x);
    float c1 = sigf(si.y*0.125f + bi.y) * tanh_fast(su.y*0.125f + bu.y);
    float h0 = sigf(so.x*0.125f + bo.x) * tanh_fast(c0);
    float h1 = sigf(so.y*0.125f + bo.y) * tanh_fast(c1);
    size_t base = (size_t)b * NN * HID + (size_t)gnode * HID + 2*t;
    *(__nv_bfloat162*)&g_hb[base] = __floats2bfloat162_rn(h0, h1);
    *(float2*)&g_c[base] = make_float2(c0, c1);
}

// ------- activation for internal nodes: reads g_iou + 4 cc rows (fused c_sum) ----
__global__ void act_kernel(const float* __restrict__ bi1, const float* __restrict__ bi2,
                           int start, int rpt, int ccnt) {
    int b = blockIdx.z;
    const float* bias = b ? bi2 : bi1;
    int r = blockIdx.x, j = threadIdx.x;
    int tree = r / rpt, lp = r % rpt;
    const float* iou = g_iou + (size_t)b * NINT * IOUW + (size_t)r * IOUW;
    float iv = iou[j]       + bias[j];
    float ov = iou[256 + j] + bias[256 + j];
    float uv = iou[512 + j] + bias[512 + j];
    const float* ccp = g_cc + (size_t)b * NLEAF * HID + ((size_t)(tree * ccnt + 4 * lp)) * HID + j;
    float cs = ccp[0] + ccp[256] + ccp[512] + ccp[768];
    float c = sigf(iv) * tanh_fast(uv) + cs;
    float h = sigf(ov) * tanh_fast(c);
    int g = tree * NPT + start + lp;
    size_t base = (size_t)b * NN * HID + (size_t)g * HID + j;
    g_hb[base] = __float2bfloat16(h);
    g_c [base] = c;
}

// ------------- readout: mean-h per tree, relu, concat @ Wf, leaky, softmax -----
__global__ void readout_kernel(const float* __restrict__ Wf, const float* __restrict__ bf,
                               float* __restrict__ out) {
    int t = blockIdx.x, j = threadIdx.x;
    float s1 = 0.f, s2 = 0.f;
    size_t base = (size_t)t * NPT * HID + j;
    for (int n = 0; n < NPT; n++) {
        s1 += __bfloat162float(g_hb[base + (size_t)n * HID]);
        s2 += __bfloat162float(g_hb[(size_t)NN * HID + base + (size_t)n * HID]);
    }
    float m1 = fmaxf(s1 * (1.0f / NPT), 0.f);
    float m2 = fmaxf(s2 * (1.0f / NPT), 0.f);
    float p0 = m1 * Wf[j * 2 + 0] + m2 * Wf[(256 + j) * 2 + 0];
    float p1 = m1 * Wf[j * 2 + 1] + m2 * Wf[(256 + j) * 2 + 1];
    __shared__ float sm0[256], sm1[256];
    sm0[j] = p0; sm1[j] = p1; __syncthreads();
    for (int s = 128; s > 0; s >>= 1) {
        if (j < s) { sm0[j] += sm0[j + s]; sm1[j] += sm1[j + s]; }
        __syncthreads();
    }
    if (j == 0) {
        float l0 = sm0[0] + bf[0], l1 = sm1[0] + bf[1];
        l0 = (l0 >= 0.f) ? l0 : 0.01f * l0;
        l1 = (l1 >= 0.f) ? l1 : 0.01f * l1;
        float mx = fmaxf(l0, l1);
        float e0 = __expf(l0 - mx), e1 = __expf(l1 - mx);
        float inv = 1.0f / (e0 + e1);
        out[t * 2 + 0] = e0 * inv;
        out[t * 2 + 1] = e1 * inv;
    }
}

// -------------------------------- launch --------------------------------------
extern "C" void kernel_launch(void* const* d_in, const int* in_sizes, int n_in,
                              void* d_out, int out_size) {
    const int*   nf1   = (const int*)  d_in[0];
    const int*   nf2   = (const int*)  d_in[1];
    const float* emb1  = (const float*)d_in[2];
    const float* emb2  = (const float*)d_in[3];
    const float* Wiou1 = (const float*)d_in[4];
    const float* Wiou2 = (const float*)d_in[5];
    const float* Uiou1 = (const float*)d_in[6];
    const float* Uiou2 = (const float*)d_in[7];
    const float* UfW1  = (const float*)d_in[8];
    const float* Ufb1  = (const float*)d_in[9];
    const float* UfW2  = (const float*)d_in[10];
    const float* Ufb2  = (const float*)d_in[11];
    const float* biou1 = (const float*)d_in[12];
    const float* biou2 = (const float*)d_in[13];
    const float* Wf    = (const float*)d_in[14];
    const float* bf    = (const float*)d_in[15];
    float* out = (float*)d_out;

    float *iouS, *c, *cc;
    bf16 *Pb, *hb, *embB, *UfTb, *UiTb, *WiTb;
    cudaGetSymbolAddress((void**)&Pb,   g_Pb);
    cudaGetSymbolAddress((void**)&iouS, g_iou);
    cudaGetSymbolAddress((void**)&c,    g_c);
    cudaGetSymbolAddress((void**)&cc,   g_cc);
    cudaGetSymbolAddress((void**)&hb,   g_hb);
    cudaGetSymbolAddress((void**)&embB, g_embB);
    cudaGetSymbolAddress((void**)&UfTb, g_UfTb);
    cudaGetSymbolAddress((void**)&UiTb, g_UiTb);
    cudaGetSymbolAddress((void**)&WiTb, g_WiTb);

    const size_t Poff = (size_t)VOCAB * IOUW;
    const size_t Hoff = (size_t)NN * HID;
    const size_t Coff = (size_t)NLEAF * HID;
    const size_t Ioff = (size_t)NINT * IOUW;

    // 0) weight transpose (fp32->bf16) + emb conversion
    transpose_k<<<dim3(24, 8, 6), dim3(32, 8)>>>(
        TPair{UfW1, UfTb, 256},           TPair{UfW2, UfTb + 256*256, 256},
        TPair{Uiou1, UiTb, 768},          TPair{Uiou2, UiTb + 768*256, 768},
        TPair{Wiou1, WiTb, 768},          TPair{Wiou2, WiTb + 768*256, 768});
    conv_emb<<<(VOCAB*256 + 1023)/1024, 1024>>>(emb1, emb2);

    // 1) token tables: P[b] = emb[b] @ W_iou[b]  -> bf16
    {
        GemmArgs a0{embB,              WiTb,           nullptr, nullptr, Pb,        VOCAB, IOUW, 0, 1, 0};
        GemmArgs a1{embB + VOCAB*256,  WiTb + 768*256, nullptr, nullptr, Pb + Poff, VOCAB, IOUW, 0, 1, 0};
        mma_gemm<2><<<dim3(IOUW/128, (VOCAB + 127)/128, 2), 256>>>(a0, a1);
    }
    // 2) fused leaf gather + activation -> h,c
    leaf_act_kernel<<<dim3(NLEAF, 1, 2), 128>>>(nf1, nf2, biou1, biou2);

    const int ps_[4]   = {21, 5, 1, 0};
    const int pcnt_[4] = {64, 16, 4, 1};
    const int cs_[4]   = {85, 21, 5, 1};
    const int ccnt_[4] = {256, 64, 16, 4};

    for (int L = 0; L < 4; L++) {
        int Mc = T_TREES * ccnt_[L];
        int Mp = T_TREES * pcnt_[L];
        // forget gate: cc = sigmoid(h_child @ Uf_W + Uf_b) * c_child
        {
            GemmArgs a0{hb,        UfTb,           Ufb1, c,        cc,        Mc, 256, cs_[L], ccnt_[L], 1};
            GemmArgs a1{hb + Hoff, UfTb + 256*256, Ufb2, c + Hoff, cc + Coff, Mc, 256, cs_[L], ccnt_[L], 1};
            mma_gemm<1><<<dim3(2, (Mc + 127)/128, 2), 256>>>(a0, a1);
        }
        // parent iou = (sum of 4 child h) @ U_iou   (child sum fused into A loader)
        {
            GemmArgs a0{hb,        UiTb,           nullptr, nullptr, iouS,        Mp, IOUW, cs_[L], pcnt_[L], 2};
            GemmArgs a1{hb + Hoff, UiTb + 768*256, nullptr, nullptr, iouS + Ioff, Mp, IOUW, cs_[L], pcnt_[L], 2};
            mma_gemm<0><<<dim3(IOUW/128, (Mp + 127)/128, 2), 256>>>(a0, a1);
        }
        // activation (c_sum from 4 cc rows fused in)
        act_kernel<<<dim3(Mp, 1, 2), 256>>>(biou1, biou2, ps_[L], pcnt_[L], ccnt_[L]);
    }

    readout_kernel<<<T_TREES, 256>>>(Wf, bf, out);
}

// round 10
// speedup vs baseline: 2.8214x; 1.0983x over previous
#include <cuda_runtime.h>
#include <cuda_bf16.h>
#include <math.h>
#include <stdint.h>

// ---------------- problem constants (structure is deterministic) ----------------
#define T_TREES   150
#define NPT       341          // nodes per tree (level-order, node0 = root)
#define NN        (T_TREES*NPT)
#define HID       256
#define IOUW      768
#define VOCAB     10000
#define LEAF_LOC0 85           // leaves are local nodes [85, 341)
#define LPT       256          // leaves per tree
#define NLEAF     (T_TREES*LPT)
#define NINT      (T_TREES*64) // max parents per level (9600)

typedef __nv_bfloat16 bf16;

// ---------------- scratch (device globals; no allocation allowed) ----------------
__device__ bf16  g_Pb  [2u*VOCAB*IOUW];   // emb @ W_iou tables (bf16, L2-resident)
__device__ float g_iou [2u*NINT*IOUW];    // iou scratch (internal nodes only)
__device__ float g_c   [2u*NN*HID];
__device__ float g_cc  [2u*NLEAF*HID];    // f * c_child per edge (compact child order)
__device__ bf16  g_hb  [2u*NN*HID];       // h (bf16, GEMM A operand)
__device__ bf16  g_embB[2u*VOCAB*256];    // emb converted to bf16
__device__ bf16  g_UfTb[2u*256*256];      // Uf_W^T  [N=256,K=256] bf16
__device__ bf16  g_UiTb[2u*768*256];      // U_iou^T [N=768,K=256] bf16
__device__ bf16  g_WiTb[2u*768*256];      // W_iou^T [N=768,K=256] bf16

__device__ __forceinline__ float sigf(float x) { return 1.0f/(1.0f+__expf(-x)); }
__device__ __forceinline__ float tanh_fast(float x) {
    float y; asm("tanh.approx.f32 %0, %1;" : "=f"(y) : "f"(x)); return y;
}
__device__ __forceinline__ unsigned smem_u32(const void* p) {
    unsigned a;
    asm("{ .reg .u64 t; cvta.to.shared.u64 t, %1; cvt.u32.u64 %0, t; }" : "=r"(a) : "l"(p));
    return a;
}
__device__ __forceinline__ void cp16(unsigned dst, const void* src, int bytes) {
    asm volatile("cp.async.ca.shared.global [%0], [%1], 16, %2;"
                 :: "r"(dst), "l"(src), "r"(bytes) : "memory");
}
#define LDSM4(r0,r1,r2,r3,addr) \
    asm volatile("ldmatrix.sync.aligned.m8n8.x4.shared.b16 {%0,%1,%2,%3}, [%4];" \
        : "=r"(r0),"=r"(r1),"=r"(r2),"=r"(r3) : "r"(addr))

__device__ __forceinline__ unsigned addb2(unsigned x, unsigned y) {
    __nv_bfloat162 a = *(__nv_bfloat162*)&x, b = *(__nv_bfloat162*)&y;
    __nv_bfloat162 r = __hadd2(a, b);
    return *(unsigned*)&r;
}
__device__ __forceinline__ uint4 addb2_4(uint4 a, uint4 b) {
    uint4 r;
    r.x = addb2(a.x, b.x); r.y = addb2(a.y, b.y);
    r.z = addb2(a.z, b.z); r.w = addb2(a.w, b.w);
    return r;
}
// sum 4 consecutive bf16 rows (stride 256) at 16B granularity
__device__ __forceinline__ uint4 bsum4(const bf16* p) {
    uint4 a = *(const uint4*)p, b = *(const uint4*)(p + 256);
    uint4 c = *(const uint4*)(p + 512), d = *(const uint4*)(p + 768);
    return addb2_4(addb2_4(a, b), addb2_4(c, d));
}

// ---------------- bf16 mma GEMM: C[M,Ntot] = A[M,256] @ Bt[Ntot,256]^T -----------
// BM=BN=128, BK=32, 256 threads = 8 warps (2 M x 4 N), warp tile 64x32.
// mode: 0 direct rows; 1 node-mapped rows; 2 on-the-fly 4-child-row sum
struct GemmArgs {
    const bf16* A; const bf16* Bt; const float* bias; const float* Cst;
    void* Out; int M; int Ntot; int start; int rpt; int mode;
};
__device__ __forceinline__ int rmap(const GemmArgs& a, int r) {
    return (a.mode == 1) ? ((r / a.rpt) * NPT + a.start + (r % a.rpt)) : r;
}

#define STRB 80u   // smem row stride bytes (40 bf16): conflict-free for ldmatrix

template<int EPI>   // 0: fp32 store ; 1: fgate sig(acc+bias)*Cst -> fp32 ; 2: bf16 store
__global__ __launch_bounds__(256, 2)
void mma_gemm(GemmArgs a0, GemmArgs a1) {
    GemmArgs a = (blockIdx.z == 0) ? a0 : a1;
    __shared__ __align__(16) char As[2][128 * STRB];
    __shared__ __align__(16) char Bs[2][128 * STRB];
    int tid = threadIdx.x, lane = tid & 31, wid = tid >> 5;
    int wm = wid >> 2, wn = wid & 3;
    int qr = lane >> 2, qc = lane & 3;
    int m0 = blockIdx.y * 128, n0 = blockIdx.x * 128;

    int lrow = tid >> 1, lhalf = tid & 1;
    int gr = m0 + lrow;
    const bf16* Ap = nullptr;
    if (gr < a.M) {
        if (a.mode == 2)
            Ap = a.A + (size_t)((gr / a.rpt) * NPT + a.start + 4 * (gr % a.rpt)) * 256 + lhalf * 16;
        else
            Ap = a.A + (size_t)rmap(a, gr) * 256 + lhalf * 16;
    }
    const bf16* ApSafe = Ap ? Ap : a.A;
    int abytes = Ap ? 16 : 0;
    const bf16* Bp = a.Bt + (size_t)(n0 + lrow) * 256 + lhalf * 16;
    unsigned dAl = smem_u32(As) + lrow * STRB + lhalf * 32u;
    unsigned dBl = smem_u32(Bs) + lrow * STRB + lhalf * 32u;
    const unsigned stageB = 128u * STRB;

    unsigned aRowOff = (((lane >> 3) & 1) * 8 + (lane & 7)) * STRB + (lane >> 4) * 16u;
    unsigned bRowOff = (((lane >> 4) << 3) + (lane & 7)) * STRB + ((lane >> 3) & 1) * 16u;
    unsigned aBase = smem_u32(As) + (wm * 64) * STRB + aRowOff;
    unsigned bBase = smem_u32(Bs) + (wn * 32) * STRB + bRowOff;

    float acc[4][4][4];
    #pragma unroll
    for (int mt = 0; mt < 4; mt++)
        #pragma unroll
        for (int nt = 0; nt < 4; nt++)
            #pragma unroll
            for (int i = 0; i < 4; i++) acc[mt][nt][i] = 0.f;

    if (a.mode == 2) {
        uint4 z = make_uint4(0,0,0,0);
        uint4 s0 = Ap ? bsum4(Ap)     : z;
        uint4 s1 = Ap ? bsum4(Ap + 8) : z;
        *(uint4*)(&As[0][lrow * STRB + lhalf * 32u])      = s0;
        *(uint4*)(&As[0][lrow * STRB + lhalf * 32u + 16]) = s1;
    } else {
        cp16(dAl,      ApSafe,     abytes);
        cp16(dAl + 16, ApSafe + 8, abytes);
    }
    cp16(dBl,      Bp,     16);
    cp16(dBl + 16, Bp + 8, 16);
    asm volatile("cp.async.commit_group;" ::: "memory");

    #pragma unroll
    for (int c = 0; c < 8; c++) {
        if (c < 7) {
            unsigned st = (c + 1) & 1;
            int kc = (c + 1) * 32;
            if (a.mode == 2) {
                uint4 z = make_uint4(0,0,0,0);
                uint4 s0 = Ap ? bsum4(Ap + kc)     : z;
                uint4 s1 = Ap ? bsum4(Ap + kc + 8) : z;
                *(uint4*)(&As[st][lrow * STRB + lhalf * 32u])      = s0;
                *(uint4*)(&As[st][lrow * STRB + lhalf * 32u + 16]) = s1;
            } else {
                cp16(dAl + st * stageB,      ApSafe + kc,     abytes);
                cp16(dAl + st * stageB + 16, ApSafe + kc + 8, abytes);
            }
            cp16(dBl + st * stageB,      Bp + kc,     16);
            cp16(dBl + st * stageB + 16, Bp + kc + 8, 16);
            asm volatile("cp.async.commit_group;" ::: "memory");
            asm volatile("cp.async.wait_group 1;" ::: "memory");
        } else {
            asm volatile("cp.async.wait_group 0;" ::: "memory");
        }
        __syncthreads();

        unsigned aS = aBase + (c & 1) * stageB;
        unsigned bS = bBase + (c & 1) * stageB;
        #pragma unroll
        for (int ks = 0; ks < 2; ks++) {
            unsigned koff = ks * 32u;
            unsigned af[4][4], bfr[4][2];
            #pragma unroll
            for (int mt = 0; mt < 4; mt++)
                LDSM4(af[mt][0], af[mt][1], af[mt][2], af[mt][3],
                      aS + mt * 16u * STRB + koff);
            LDSM4(bfr[0][0], bfr[0][1], bfr[1][0], bfr[1][1], bS + koff);
            LDSM4(bfr[2][0], bfr[2][1], bfr[3][0], bfr[3][1], bS + 16u * STRB + koff);
            #pragma unroll
            for (int mt = 0; mt < 4; mt++)
                #pragma unroll
                for (int nt = 0; nt < 4; nt++) {
                    float* d = acc[mt][nt];
                    asm volatile(
                        "mma.sync.aligned.m16n8k16.row.col.f32.bf16.bf16.f32 "
                        "{%0,%1,%2,%3}, {%4,%5,%6,%7}, {%8,%9}, {%0,%1,%2,%3};"
                        : "+f"(d[0]), "+f"(d[1]), "+f"(d[2]), "+f"(d[3])
                        : "r"(af[mt][0]), "r"(af[mt][1]), "r"(af[mt][2]), "r"(af[mt][3]),
                          "r"(bfr[nt][0]), "r"(bfr[nt][1]));
                }
        }
        __syncthreads();
    }

    #pragma unroll
    for (int mt = 0; mt < 4; mt++) {
        #pragma unroll
        for (int half = 0; half < 2; half++) {
            int r = m0 + wm * 64 + mt * 16 + qr + half * 8;
            if (r >= a.M) continue;
            int ridx = rmap(a, r);
            #pragma unroll
            for (int nt = 0; nt < 4; nt++) {
                int col = n0 + wn * 32 + nt * 8 + qc * 2;
                float v0 = acc[mt][nt][half * 2 + 0];
                float v1 = acc[mt][nt][half * 2 + 1];
                if (EPI == 1) {
                    float b0 = __ldg(&a.bias[col]), b1 = __ldg(&a.bias[col + 1]);
                    const float* cst = a.Cst + (size_t)ridx * 256 + col;
                    float2 o;
                    o.x = sigf(v0 + b0) * cst[0];
                    o.y = sigf(v1 + b1) * cst[1];
                    *(float2*)((float*)a.Out + (size_t)r * 256 + col) = o;
                } else if (EPI == 2) {
                    __nv_bfloat162 o = __floats2bfloat162_rn(v0, v1);
                    *(__nv_bfloat162*)((bf16*)a.Out + (size_t)r * a.Ntot + col) = o;
                } else {
                    *(float2*)((float*)a.Out + (size_t)r * a.Ntot + col) = make_float2(v0, v1);
                }
            }
        }
    }
}

// ---------------- weight transpose: S[256,N] fp32 -> D[N,256] bf16 ---------------
struct TPair { const float* s; bf16* d; int n; };
__global__ void transpose_k(TPair p0, TPair p1, TPair p2, TPair p3, TPair p4, TPair p5) {
    TPair p;
    switch (blockIdx.z) {
        case 0: p = p0; break; case 1: p = p1; break; case 2: p = p2; break;
        case 3: p = p3; break; case 4: p = p4; break; default: p = p5; break;
    }
    int x0 = blockIdx.x * 32;
    if (x0 >= p.n) return;
    int y0 = blockIdx.y * 32;
    __shared__ float t[32][33];
    #pragma unroll
    for (int s = 0; s < 32; s += 8)
        t[threadIdx.y + s][threadIdx.x] = p.s[(size_t)(y0 + threadIdx.y + s) * p.n + x0 + threadIdx.x];
    __syncthreads();
    #pragma unroll
    for (int s = 0; s < 32; s += 8)
        p.d[(size_t)(x0 + threadIdx.y + s) * 256 + y0 + threadIdx.x] =
            __float2bfloat16(t[threadIdx.x][threadIdx.y + s]);
}

// ---------------- emb fp32 -> bf16 ----------------------------------------------
__global__ void conv_emb(const float* __restrict__ e1, const float* __restrict__ e2) {
    int i = blockIdx.x * 1024 + threadIdx.x;
    const unsigned n = VOCAB * 256u;
    if (i < (int)n) {
        g_embB[i]     = __float2bfloat16(e1[i]);
        g_embB[n + i] = __float2bfloat16(e2[i]);
    }
}

// ------- fused leaf v3: bf16x2 tree-sum of 8 P rows (uint4 loads) -> activation ---
__global__ __launch_bounds__(128)
void leaf_act_kernel(const int* __restrict__ nf1, const int* __restrict__ nf2,
                     const float* __restrict__ bi1, const float* __restrict__ bi2) {
    int b = blockIdx.z;
    const int* nf = b ? nf2 : nf1;
    const float* bias = b ? bi2 : bi1;
    int leaf = blockIdx.x;
    int tree = leaf >> 8, ll = leaf & 255;
    int gnode = tree * NPT + LEAF_LOC0 + ll;
    __shared__ int toks[8];
    __shared__ unsigned s_acc[384];
    int t = threadIdx.x;
    if (t < 8) toks[t] = nf[gnode * 8 + t];
    __syncthreads();

    if (t < 96) {
        // thread covers u32 words [4t, 4t+4) of the 384-word (768 bf16) row
        const uint4* P = (const uint4*)(g_Pb + (size_t)b * VOCAB * IOUW);
        unsigned w = (unsigned)t;  // uint4 index within row (row = 96 uint4)
        uint4 v[8];
        #pragma unroll
        for (int s = 0; s < 8; s++) v[s] = __ldg(P + (size_t)toks[s] * 96 + w);
        uint4 sum = addb2_4(addb2_4(addb2_4(v[0], v[1]), addb2_4(v[2], v[3])),
                            addb2_4(addb2_4(v[4], v[5]), addb2_4(v[6], v[7])));
        *(uint4*)&s_acc[t * 4] = sum;
    }
    __syncthreads();

    // activation: thread t handles cols 2t, 2t+1
    float2 si = __bfloat1622float2(*(__nv_bfloat162*)&s_acc[t]);
    float2 so = __bfloat1622float2(*(__nv_bfloat162*)&s_acc[128 + t]);
    float2 su = __bfloat1622float2(*(__nv_bfloat162*)&s_acc[256 + t]);
    float2 bi = *(const float2*)&bias[2*t];
    float2 bo = *(const float2*)&bias[256 + 2*t];
    float2 bu = *(const float2*)&bias[512 + 2*t];
    float c0 = sigf(si.x*0.125f + bi.x) * tanh_fast(su.x*0.125f + bu.x);
    float c1 = sigf(si.y*0.125f + bi.y) * tanh_fast(su.y*0.125f + bu.y);
    float h0 = sigf(so.x*0.125f + bo.x) * tanh_fast(c0);
    float h1 = sigf(so.y*0.125f + bo.y) * tanh_fast(c1);
    size_t base = (size_t)b * NN * HID + (size_t)gnode * HID + 2*t;
    *(__nv_bfloat162*)&g_hb[base] = __floats2bfloat162_rn(h0, h1);
    *(float2*)&g_c[base] = make_float2(c0, c1);
}

// ------- act v2: float4 vectorized, 4 rows per block (64 threads per row) --------
__global__ __launch_bounds__(256)
void act_kernel(const float* __restrict__ bi1, const float* __restrict__ bi2,
                int Mp, int start, int rpt, int ccnt) {
    int b = blockIdx.z;
    const float* bias = b ? bi2 : bi1;
    int r = blockIdx.x * 4 + (threadIdx.x >> 6);
    if (r >= Mp) return;
    int j = (threadIdx.x & 63) * 4;
    int tree = r / rpt, lp = r % rpt;
    const float* iou = g_iou + (size_t)b * NINT * IOUW + (size_t)r * IOUW;
    float4 iv = *(const float4*)(iou + j);
    float4 ov = *(const float4*)(iou + 256 + j);
    float4 uv = *(const float4*)(iou + 512 + j);
    float4 bi = *(const float4*)(bias + j);
    float4 bo = *(const float4*)(bias + 256 + j);
    float4 bu = *(const float4*)(bias + 512 + j);
    const float* ccp = g_cc + (size_t)b * NLEAF * HID + ((size_t)(tree * ccnt + 4 * lp)) * HID + j;
    float4 c0 = *(const float4*)(ccp);
    float4 c1 = *(const float4*)(ccp + 256);
    float4 c2 = *(const float4*)(ccp + 512);
    float4 c3 = *(const float4*)(ccp + 768);
    float cs[4] = { c0.x+c1.x+c2.x+c3.x, c0.y+c1.y+c2.y+c3.y,
                    c0.z+c1.z+c2.z+c3.z, c0.w+c1.w+c2.w+c3.w };
    float ivv[4] = {iv.x+bi.x, iv.y+bi.y, iv.z+bi.z, iv.w+bi.w};
    float ovv[4] = {ov.x+bo.x, ov.y+bo.y, ov.z+bo.z, ov.w+bo.w};
    float uvv[4] = {uv.x+bu.x, uv.y+bu.y, uv.z+bu.z, uv.w+bu.w};
    float cr[4], hr[4];
    #pragma unroll
    for (int k = 0; k < 4; k++) {
        cr[k] = sigf(ivv[k]) * tanh_fast(uvv[k]) + cs[k];
        hr[k] = sigf(ovv[k]) * tanh_fast(cr[k]);
    }
    int g = tree * NPT + start + lp;
    size_t base = (size_t)b * NN * HID + (size_t)g * HID + j;
    uint2 hb2;
    __nv_bfloat162 h01 = __floats2bfloat162_rn(hr[0], hr[1]);
    __nv_bfloat162 h23 = __floats2bfloat162_rn(hr[2], hr[3]);
    hb2.x = *(unsigned*)&h01; hb2.y = *(unsigned*)&h23;
    *(uint2*)&g_hb[base] = hb2;
    *(float4*)&g_c[base] = make_float4(cr[0], cr[1], cr[2], cr[3]);
}

// ------- readout v2: both branches in parallel halves, bf16x2 loads --------------
__global__ __launch_bounds__(256)
void readout_kernel(const float* __restrict__ Wf, const float* __restrict__ bf,
                    float* __restrict__ out) {
    int t = blockIdx.x;
    int br = threadIdx.x >> 7;          // 0 or 1
    int j = threadIdx.x & 127;          // cols 2j, 2j+1
    const unsigned* hp = (const unsigned*)(g_hb + (size_t)br * NN * HID
                                           + (size_t)t * NPT * HID) + j;
    float s0 = 0.f, s1 = 0.f;
    for (int n = 0; n < NPT; n++) {
        float2 v = __bfloat1622float2(*(__nv_bfloat162*)&hp[n * 128]);
        s0 += v.x; s1 += v.y;
    }
    float m0 = fmaxf(s0 * (1.0f / NPT), 0.f);
    float m1 = fmaxf(s1 * (1.0f / NPT), 0.f);
    int col0 = br * 256 + 2 * j;
    float p0 = m0 * Wf[col0 * 2 + 0] + m1 * Wf[(col0 + 1) * 2 + 0];
    float p1 = m0 * Wf[col0 * 2 + 1] + m1 * Wf[(col0 + 1) * 2 + 1];
    __shared__ float sm0[256], sm1[256];
    sm0[threadIdx.x] = p0; sm1[threadIdx.x] = p1; __syncthreads();
    for (int s = 128; s > 0; s >>= 1) {
        if (threadIdx.x < s) {
            sm0[threadIdx.x] += sm0[threadIdx.x + s];
            sm1[threadIdx.x] += sm1[threadIdx.x + s];
        }
        __syncthreads();
    }
    if (threadIdx.x == 0) {
        float l0 = sm0[0] + bf[0], l1 = sm1[0] + bf[1];
        l0 = (l0 >= 0.f) ? l0 : 0.01f * l0;
        l1 = (l1 >= 0.f) ? l1 : 0.01f * l1;
        float mx = fmaxf(l0, l1);
        float e0 = __expf(l0 - mx), e1 = __expf(l1 - mx);
        float inv = 1.0f / (e0 + e1);
        out[t * 2 + 0] = e0 * inv;
        out[t * 2 + 1] = e1 * inv;
    }
}

// -------------------------------- launch --------------------------------------
extern "C" void kernel_launch(void* const* d_in, const int* in_sizes, int n_in,
                              void* d_out, int out_size) {
    const int*   nf1   = (const int*)  d_in[0];
    const int*   nf2   = (const int*)  d_in[1];
    const float* emb1  = (const float*)d_in[2];
    const float* emb2  = (const float*)d_in[3];
    const float* Wiou1 = (const float*)d_in[4];
    const float* Wiou2 = (const float*)d_in[5];
    const float* Uiou1 = (const float*)d_in[6];
    const float* Uiou2 = (const float*)d_in[7];
    const float* UfW1  = (const float*)d_in[8];
    const float* Ufb1  = (const float*)d_in[9];
    const float* UfW2  = (const float*)d_in[10];
    const float* Ufb2  = (const float*)d_in[11];
    const float* biou1 = (const float*)d_in[12];
    const float* biou2 = (const float*)d_in[13];
    const float* Wf    = (const float*)d_in[14];
    const float* bf    = (const float*)d_in[15];
    float* out = (float*)d_out;

    float *iouS, *c, *cc;
    bf16 *Pb, *hb, *embB, *UfTb, *UiTb, *WiTb;
    cudaGetSymbolAddress((void**)&Pb,   g_Pb);
    cudaGetSymbolAddress((void**)&iouS, g_iou);
    cudaGetSymbolAddress((void**)&c,    g_c);
    cudaGetSymbolAddress((void**)&cc,   g_cc);
    cudaGetSymbolAddress((void**)&hb,   g_hb);
    cudaGetSymbolAddress((void**)&embB, g_embB);
    cudaGetSymbolAddress((void**)&UfTb, g_UfTb);
    cudaGetSymbolAddress((void**)&UiTb, g_UiTb);
    cudaGetSymbolAddress((void**)&WiTb, g_WiTb);

    const size_t Poff = (size_t)VOCAB * IOUW;
    const size_t Hoff = (size_t)NN * HID;
    const size_t Coff = (size_t)NLEAF * HID;
    const size_t Ioff = (size_t)NINT * IOUW;

    // 0) weight transpose (fp32->bf16) + emb conversion
    transpose_k<<<dim3(24, 8, 6), dim3(32, 8)>>>(
        TPair{UfW1, UfTb, 256},           TPair{UfW2, UfTb + 256*256, 256},
        TPair{Uiou1, UiTb, 768},          TPair{Uiou2, UiTb + 768*256, 768},
        TPair{Wiou1, WiTb, 768},          TPair{Wiou2, WiTb + 768*256, 768});
    conv_emb<<<(VOCAB*256 + 1023)/1024, 1024>>>(emb1, emb2);

    // 1) token tables: P[b] = emb[b] @ W_iou[b]  -> bf16
    {
        GemmArgs a0{embB,              WiTb,           nullptr, nullptr, Pb,        VOCAB, IOUW, 0, 1, 0};
        GemmArgs a1{embB + VOCAB*256,  WiTb + 768*256, nullptr, nullptr, Pb + Poff, VOCAB, IOUW, 0, 1, 0};
        mma_gemm<2><<<dim3(IOUW/128, (VOCAB + 127)/128, 2), 256>>>(a0, a1);
    }
    // 2) fused leaf gather + activation -> h,c
    leaf_act_kernel<<<dim3(NLEAF, 1, 2), 128>>>(nf1, nf2, biou1, biou2);

    const int ps_[4]   = {21, 5, 1, 0};
    const int pcnt_[4] = {64, 16, 4, 1};
    const int cs_[4]   = {85, 21, 5, 1};
    const int ccnt_[4] = {256, 64, 16, 4};

    for (int L = 0; L < 4; L++) {
        int Mc = T_TREES * ccnt_[L];
        int Mp = T_TREES * pcnt_[L];
        // forget gate: cc = sigmoid(h_child @ Uf_W + Uf_b) * c_child
        {
            GemmArgs a0{hb,        UfTb,           Ufb1, c,        cc,        Mc, 256, cs_[L], ccnt_[L], 1};
            GemmArgs a1{hb + Hoff, UfTb + 256*256, Ufb2, c + Hoff, cc + Coff, Mc, 256, cs_[L], ccnt_[L], 1};
            mma_gemm<1><<<dim3(2, (Mc + 127)/128, 2), 256>>>(a0, a1);
        }
        // parent iou = (sum of 4 child h) @ U_iou   (child sum fused into A loader)
        {
            GemmArgs a0{hb,        UiTb,           nullptr, nullptr, iouS,        Mp, IOUW, cs_[L], pcnt_[L], 2};
            GemmArgs a1{hb + Hoff, UiTb + 768*256, nullptr, nullptr, iouS + Ioff, Mp, IOUW, cs_[L], pcnt_[L], 2};
            mma_gemm<0><<<dim3(IOUW/128, (Mp + 127)/128, 2), 256>>>(a0, a1);
        }
        // activation (c_sum from 4 cc rows fused in)
        act_kernel<<<dim3((Mp + 3)/4, 1, 2), 256>>>(biou1, biou2, Mp, ps_[L], pcnt_[L], ccnt_[L]);
    }

    readout_kernel<<<T_TREES, 256>>>(Wf, bf, out);
}

// round 11
// speedup vs baseline: 3.3591x; 1.1906x over previous
#include <cuda_runtime.h>
#include <cuda_bf16.h>
#include <math.h>
#include <stdint.h>

// ---------------- problem constants (structure is deterministic) ----------------
#define T_TREES   150
#define NPT       341
#define NN        (T_TREES*NPT)
#define HID       256
#define IOUW      768
#define VOCAB     10000
#define LEAF_LOC0 85
#define LPT       256
#define NLEAF     (T_TREES*LPT)
#define NINT      (T_TREES*64)

typedef __nv_bfloat16 bf16;

// ---------------- scratch ------------------------------------------------------
__device__ bf16  g_Pb  [2u*VOCAB*IOUW];   // emb @ W_iou tables (bf16, L2-resident)
__device__ float g_iou [2u*NINT*IOUW];
__device__ float g_c   [2u*NN*HID];
__device__ float g_cs  [2u*NINT*HID];     // per-parent c_sum (written by fgate epilogue)
__device__ bf16  g_hb  [2u*NN*HID];
__device__ bf16  g_embB[2u*VOCAB*256];
__device__ bf16  g_UfTb[2u*256*256];
__device__ bf16  g_UiTb[2u*768*256];
__device__ bf16  g_WiTb[2u*768*256];

__device__ __forceinline__ float tanh_fast(float x) {
    float y; asm("tanh.approx.f32 %0, %1;" : "=f"(y) : "f"(x)); return y;
}
__device__ __forceinline__ float sigt(float x) {           // 1 MUFU sigmoid
    return fmaf(0.5f, tanh_fast(0.5f * x), 0.5f);
}
__device__ __forceinline__ unsigned smem_u32(const void* p) {
    unsigned a;
    asm("{ .reg .u64 t; cvta.to.shared.u64 t, %1; cvt.u32.u64 %0, t; }" : "=r"(a) : "l"(p));
    return a;
}
__device__ __forceinline__ void cp16(unsigned dst, const void* src, int bytes) {
    asm volatile("cp.async.ca.shared.global [%0], [%1], 16, %2;"
                 :: "r"(dst), "l"(src), "r"(bytes) : "memory");
}
#define LDSM4(r0,r1,r2,r3,addr) \
    asm volatile("ldmatrix.sync.aligned.m8n8.x4.shared.b16 {%0,%1,%2,%3}, [%4];" \
        : "=r"(r0),"=r"(r1),"=r"(r2),"=r"(r3) : "r"(addr))

__device__ __forceinline__ unsigned addb2(unsigned x, unsigned y) {
    __nv_bfloat162 a = *(__nv_bfloat162*)&x, b = *(__nv_bfloat162*)&y;
    __nv_bfloat162 r = __hadd2(a, b);
    return *(unsigned*)&r;
}
__device__ __forceinline__ uint4 addb2_4(uint4 a, uint4 b) {
    uint4 r;
    r.x = addb2(a.x, b.x); r.y = addb2(a.y, b.y);
    r.z = addb2(a.z, b.z); r.w = addb2(a.w, b.w);
    return r;
}
__device__ __forceinline__ uint4 bsum4(const bf16* p) {
    uint4 a = *(const uint4*)p, b = *(const uint4*)(p + 256);
    uint4 c = *(const uint4*)(p + 512), d = *(const uint4*)(p + 768);
    return addb2_4(addb2_4(a, b), addb2_4(c, d));
}

// ---------------- bf16 mma GEMM body -------------------------------------------
// BM=BN=128, BK=32, 256 threads = 8 warps (2 M x 4 N), warp tile 64x32.
// mode: 0 direct rows; 1 node-mapped rows; 2 on-the-fly 4-child-row sum
// epi : 0 fp32 store; 1 fgate sig*c + in-warp 4-row reduce -> cs[parent]; 2 bf16 store
struct GemmArgs {
    const bf16* A; const bf16* Bt; const float* bias; const float* Cst;
    void* Out; int M; int Ntot; int start; int rpt; int mode; int epi;
};
__device__ __forceinline__ int rmap(const GemmArgs& a, int r) {
    return (a.mode == 1) ? ((r / a.rpt) * NPT + a.start + (r % a.rpt)) : r;
}

#define STRB 80u

__device__ __forceinline__ void gemm_body(const GemmArgs& a, int bx, int by) {
    __shared__ __align__(16) char As[2][128 * STRB];
    __shared__ __align__(16) char Bs[2][128 * STRB];
    int tid = threadIdx.x, lane = tid & 31, wid = tid >> 5;
    int wm = wid >> 2, wn = wid & 3;
    int qr = lane >> 2, qc = lane & 3;
    int m0 = by * 128, n0 = bx * 128;

    int lrow = tid >> 1, lhalf = tid & 1;
    int gr = m0 + lrow;
    const bf16* Ap = nullptr;
    if (gr < a.M) {
        if (a.mode == 2)
            Ap = a.A + (size_t)((gr / a.rpt) * NPT + a.start + 4 * (gr % a.rpt)) * 256 + lhalf * 16;
        else
            Ap = a.A + (size_t)rmap(a, gr) * 256 + lhalf * 16;
    }
    const bf16* ApSafe = Ap ? Ap : a.A;
    int abytes = Ap ? 16 : 0;
    const bf16* Bp = a.Bt + (size_t)(n0 + lrow) * 256 + lhalf * 16;
    unsigned dAl = smem_u32(As) + lrow * STRB + lhalf * 32u;
    unsigned dBl = smem_u32(Bs) + lrow * STRB + lhalf * 32u;
    const unsigned stageB = 128u * STRB;

    unsigned aRowOff = (((lane >> 3) & 1) * 8 + (lane & 7)) * STRB + (lane >> 4) * 16u;
    unsigned bRowOff = (((lane >> 4) << 3) + (lane & 7)) * STRB + ((lane >> 3) & 1) * 16u;
    unsigned aBase = smem_u32(As) + (wm * 64) * STRB + aRowOff;
    unsigned bBase = smem_u32(Bs) + (wn * 32) * STRB + bRowOff;

    float acc[4][4][4];
    #pragma unroll
    for (int mt = 0; mt < 4; mt++)
        #pragma unroll
        for (int nt = 0; nt < 4; nt++)
            #pragma unroll
            for (int i = 0; i < 4; i++) acc[mt][nt][i] = 0.f;

    if (a.mode == 2) {
        uint4 z = make_uint4(0,0,0,0);
        uint4 s0 = Ap ? bsum4(Ap)     : z;
        uint4 s1 = Ap ? bsum4(Ap + 8) : z;
        *(uint4*)(&As[0][lrow * STRB + lhalf * 32u])      = s0;
        *(uint4*)(&As[0][lrow * STRB + lhalf * 32u + 16]) = s1;
    } else {
        cp16(dAl,      ApSafe,     abytes);
        cp16(dAl + 16, ApSafe + 8, abytes);
    }
    cp16(dBl,      Bp,     16);
    cp16(dBl + 16, Bp + 8, 16);
    asm volatile("cp.async.commit_group;" ::: "memory");

    #pragma unroll
    for (int c = 0; c < 8; c++) {
        if (c < 7) {
            unsigned st = (c + 1) & 1;
            int kc = (c + 1) * 32;
            if (a.mode == 2) {
                uint4 z = make_uint4(0,0,0,0);
                uint4 s0 = Ap ? bsum4(Ap + kc)     : z;
                uint4 s1 = Ap ? bsum4(Ap + kc + 8) : z;
                *(uint4*)(&As[st][lrow * STRB + lhalf * 32u])      = s0;
                *(uint4*)(&As[st][lrow * STRB + lhalf * 32u + 16]) = s1;
            } else {
                cp16(dAl + st * stageB,      ApSafe + kc,     abytes);
                cp16(dAl + st * stageB + 16, ApSafe + kc + 8, abytes);
            }
            cp16(dBl + st * stageB,      Bp + kc,     16);
            cp16(dBl + st * stageB + 16, Bp + kc + 8, 16);
            asm volatile("cp.async.commit_group;" ::: "memory");
            asm volatile("cp.async.wait_group 1;" ::: "memory");
        } else {
            asm volatile("cp.async.wait_group 0;" ::: "memory");
        }
        __syncthreads();

        unsigned aS = aBase + (c & 1) * stageB;
        unsigned bS = bBase + (c & 1) * stageB;
        #pragma unroll
        for (int ks = 0; ks < 2; ks++) {
            unsigned koff = ks * 32u;
            unsigned af[4][4], bfr[4][2];
            #pragma unroll
            for (int mt = 0; mt < 4; mt++)
                LDSM4(af[mt][0], af[mt][1], af[mt][2], af[mt][3],
                      aS + mt * 16u * STRB + koff);
            LDSM4(bfr[0][0], bfr[0][1], bfr[1][0], bfr[1][1], bS + koff);
            LDSM4(bfr[2][0], bfr[2][1], bfr[3][0], bfr[3][1], bS + 16u * STRB + koff);
            #pragma unroll
            for (int mt = 0; mt < 4; mt++)
                #pragma unroll
                for (int nt = 0; nt < 4; nt++) {
                    float* d = acc[mt][nt];
                    asm volatile(
                        "mma.sync.aligned.m16n8k16.row.col.f32.bf16.bf16.f32 "
                        "{%0,%1,%2,%3}, {%4,%5,%6,%7}, {%8,%9}, {%0,%1,%2,%3};"
                        : "+f"(d[0]), "+f"(d[1]), "+f"(d[2]), "+f"(d[3])
                        : "r"(af[mt][0]), "r"(af[mt][1]), "r"(af[mt][2]), "r"(af[mt][3]),
                          "r"(bfr[nt][0]), "r"(bfr[nt][1]));
                }
        }
        __syncthreads();
    }

    if (a.epi == 1) {
        // fgate: o = sig(acc+bias)*c_child, then sum the 4 child rows of each
        // parent with two xor-butterflies; lane qr%4==0 writes cs[parent].
        int base0 = m0 + wm * 64;
        #pragma unroll
        for (int mt = 0; mt < 4; mt++) {
            #pragma unroll
            for (int half = 0; half < 2; half++) {
                int gb = base0 + mt * 16 + half * 8 + ((lane & 16) >> 2); // group base
                bool valid = gb < a.M;
                int r = gb + ((lane >> 2) & 3);
                int rr = valid ? rmap(a, r) : 0;
                #pragma unroll
                for (int nt = 0; nt < 4; nt++) {
                    int col = n0 + wn * 32 + nt * 8 + qc * 2;
                    float o0 = 0.f, o1 = 0.f;
                    if (valid) {
                        const float* cp = a.Cst + (size_t)rr * 256 + col;
                        o0 = sigt(acc[mt][nt][half*2+0] + __ldg(&a.bias[col]))     * cp[0];
                        o1 = sigt(acc[mt][nt][half*2+1] + __ldg(&a.bias[col + 1])) * cp[1];
                    }
                    o0 += __shfl_xor_sync(0xffffffffu, o0, 4);
                    o0 += __shfl_xor_sync(0xffffffffu, o0, 8);
                    o1 += __shfl_xor_sync(0xffffffffu, o1, 4);
                    o1 += __shfl_xor_sync(0xffffffffu, o1, 8);
                    if (valid && (lane & 12) == 0) {
                        int pr = gb >> 2;
                        *(float2*)((float*)a.Out + (size_t)pr * 256 + col) = make_float2(o0, o1);
                    }
                }
            }
        }
    } else {
        #pragma unroll
        for (int mt = 0; mt < 4; mt++) {
            #pragma unroll
            for (int half = 0; half < 2; half++) {
                int r = m0 + wm * 64 + mt * 16 + qr + half * 8;
                if (r >= a.M) continue;
                #pragma unroll
                for (int nt = 0; nt < 4; nt++) {
                    int col = n0 + wn * 32 + nt * 8 + qc * 2;
                    float v0 = acc[mt][nt][half * 2 + 0];
                    float v1 = acc[mt][nt][half * 2 + 1];
                    if (a.epi == 2) {
                        __nv_bfloat162 o = __floats2bfloat162_rn(v0, v1);
                        *(__nv_bfloat162*)((bf16*)a.Out + (size_t)r * a.Ntot + col) = o;
                    } else {
                        *(float2*)((float*)a.Out + (size_t)r * a.Ntot + col) = make_float2(v0, v1);
                    }
                }
            }
        }
    }
}

__global__ __launch_bounds__(256, 2)
void mma_gemm(GemmArgs a0, GemmArgs a1) {
    gemm_body(blockIdx.z ? a1 : a0, blockIdx.x, blockIdx.y);
}

// merged per-level launch: fgate blocks [0,nf), U_iou blocks [nf, nf+nu)
__global__ __launch_bounds__(256, 2)
void level_gemm(GemmArgs f0, GemmArgs f1, GemmArgs u0, GemmArgs u1, int nf) {
    int bid = blockIdx.x;
    if (bid < nf) {
        gemm_body(blockIdx.z ? f1 : f0, bid & 1, bid >> 1);
    } else {
        int r2 = bid - nf;
        gemm_body(blockIdx.z ? u1 : u0, r2 % 6, r2 / 6);
    }
}

// ---------------- weight transpose: S[256,N] fp32 -> D[N,256] bf16 ---------------
struct TPair { const float* s; bf16* d; int n; };
__global__ void transpose_k(TPair p0, TPair p1, TPair p2, TPair p3, TPair p4, TPair p5) {
    TPair p;
    switch (blockIdx.z) {
        case 0: p = p0; break; case 1: p = p1; break; case 2: p = p2; break;
        case 3: p = p3; break; case 4: p = p4; break; default: p = p5; break;
    }
    int x0 = blockIdx.x * 32;
    if (x0 >= p.n) return;
    int y0 = blockIdx.y * 32;
    __shared__ float t[32][33];
    #pragma unroll
    for (int s = 0; s < 32; s += 8)
        t[threadIdx.y + s][threadIdx.x] = p.s[(size_t)(y0 + threadIdx.y + s) * p.n + x0 + threadIdx.x];
    __syncthreads();
    #pragma unroll
    for (int s = 0; s < 32; s += 8)
        p.d[(size_t)(x0 + threadIdx.y + s) * 256 + y0 + threadIdx.x] =
            __float2bfloat16(t[threadIdx.x][threadIdx.y + s]);
}

__global__ void conv_emb(const float* __restrict__ e1, const float* __restrict__ e2) {
    int i = blockIdx.x * 1024 + threadIdx.x;
    const unsigned n = VOCAB * 256u;
    if (i < (int)n) {
        g_embB[i]     = __float2bfloat16(e1[i]);
        g_embB[n + i] = __float2bfloat16(e2[i]);
    }
}

// ------- fused leaf: bf16x2 tree-sum of 8 P rows -> activation -------------------
__global__ __launch_bounds__(128)
void leaf_act_kernel(const int* __restrict__ nf1, const int* __restrict__ nf2,
                     const float* __restrict__ bi1, const float* __restrict__ bi2) {
    int b = blockIdx.z;
    const int* nf = b ? nf2 : nf1;
    const float* bias = b ? bi2 : bi1;
    int leaf = blockIdx.x;
    int tree = leaf >> 8, ll = leaf & 255;
    int gnode = tree * NPT + LEAF_LOC0 + ll;
    __shared__ int toks[8];
    __shared__ unsigned s_acc[384];
    int t = threadIdx.x;
    if (t < 8) toks[t] = nf[gnode * 8 + t];
    __syncthreads();

    if (t < 96) {
        const uint4* P = (const uint4*)(g_Pb + (size_t)b * VOCAB * IOUW);
        unsigned w = (unsigned)t;
        uint4 v[8];
        #pragma unroll
        for (int s = 0; s < 8; s++) v[s] = __ldg(P + (size_t)toks[s] * 96 + w);
        uint4 sum = addb2_4(addb2_4(addb2_4(v[0], v[1]), addb2_4(v[2], v[3])),
                            addb2_4(addb2_4(v[4], v[5]), addb2_4(v[6], v[7])));
        *(uint4*)&s_acc[t * 4] = sum;
    }
    __syncthreads();

    float2 si = __bfloat1622float2(*(__nv_bfloat162*)&s_acc[t]);
    float2 so = __bfloat1622float2(*(__nv_bfloat162*)&s_acc[128 + t]);
    float2 su = __bfloat1622float2(*(__nv_bfloat162*)&s_acc[256 + t]);
    float2 bi = *(const float2*)&bias[2*t];
    float2 bo = *(const float2*)&bias[256 + 2*t];
    float2 bu = *(const float2*)&bias[512 + 2*t];
    float c0 = sigt(si.x*0.125f + bi.x) * tanh_fast(su.x*0.125f + bu.x);
    float c1 = sigt(si.y*0.125f + bi.y) * tanh_fast(su.y*0.125f + bu.y);
    float h0 = sigt(so.x*0.125f + bo.x) * tanh_fast(c0);
    float h1 = sigt(so.y*0.125f + bo.y) * tanh_fast(c1);
    size_t base = (size_t)b * NN * HID + (size_t)gnode * HID + 2*t;
    *(__nv_bfloat162*)&g_hb[base] = __floats2bfloat162_rn(h0, h1);
    *(float2*)&g_c[base] = make_float2(c0, c1);
}

// ------- act: iou row + single cs row, float4 vectorized, 4 rows per block -------
__global__ __launch_bounds__(256)
void act_kernel(const float* __restrict__ bi1, const float* __restrict__ bi2,
                int Mp, int start, int rpt) {
    int b = blockIdx.z;
    const float* bias = b ? bi2 : bi1;
    int r = blockIdx.x * 4 + (threadIdx.x >> 6);
    if (r >= Mp) return;
    int j = (threadIdx.x & 63) * 4;
    int tree = r / rpt, lp = r % rpt;
    const float* iou = g_iou + (size_t)b * NINT * IOUW + (size_t)r * IOUW;
    float4 iv = *(const float4*)(iou + j);
    float4 ov = *(const float4*)(iou + 256 + j);
    float4 uv = *(const float4*)(iou + 512 + j);
    float4 bi = *(const float4*)(bias + j);
    float4 bo = *(const float4*)(bias + 256 + j);
    float4 bu = *(const float4*)(bias + 512 + j);
    float4 cs4 = *(const float4*)(g_cs + (size_t)b * NINT * HID + (size_t)r * HID + j);
    float cs[4] = {cs4.x, cs4.y, cs4.z, cs4.w};
    float ivv[4] = {iv.x+bi.x, iv.y+bi.y, iv.z+bi.z, iv.w+bi.w};
    float ovv[4] = {ov.x+bo.x, ov.y+bo.y, ov.z+bo.z, ov.w+bo.w};
    float uvv[4] = {uv.x+bu.x, uv.y+bu.y, uv.z+bu.z, uv.w+bu.w};
    float cr[4], hr[4];
    #pragma unroll
    for (int k = 0; k < 4; k++) {
        cr[k] = sigt(ivv[k]) * tanh_fast(uvv[k]) + cs[k];
        hr[k] = sigt(ovv[k]) * tanh_fast(cr[k]);
    }
    int g = tree * NPT + start + lp;
    size_t base = (size_t)b * NN * HID + (size_t)g * HID + j;
    uint2 hb2;
    __nv_bfloat162 h01 = __floats2bfloat162_rn(hr[0], hr[1]);
    __nv_bfloat162 h23 = __floats2bfloat162_rn(hr[2], hr[3]);
    hb2.x = *(unsigned*)&h01; hb2.y = *(unsigned*)&h23;
    *(uint2*)&g_hb[base] = hb2;
    *(float4*)&g_c[base] = make_float4(cr[0], cr[1], cr[2], cr[3]);
}

// ------- readout: both branches in parallel halves, bf16x2 loads -----------------
__global__ __launch_bounds__(256)
void readout_kernel(const float* __restrict__ Wf, const float* __restrict__ bf,
                    float* __restrict__ out) {
    int t = blockIdx.x;
    int br = threadIdx.x >> 7;
    int j = threadIdx.x & 127;
    const unsigned* hp = (const unsigned*)(g_hb + (size_t)br * NN * HID
                                           + (size_t)t * NPT * HID) + j;
    float s0 = 0.f, s1 = 0.f;
    for (int n = 0; n < NPT; n++) {
        float2 v = __bfloat1622float2(*(__nv_bfloat162*)&hp[n * 128]);
        s0 += v.x; s1 += v.y;
    }
    float m0 = fmaxf(s0 * (1.0f / NPT), 0.f);
    float m1 = fmaxf(s1 * (1.0f / NPT), 0.f);
    int col0 = br * 256 + 2 * j;
    float p0 = m0 * Wf[col0 * 2 + 0] + m1 * Wf[(col0 + 1) * 2 + 0];
    float p1 = m0 * Wf[col0 * 2 + 1] + m1 * Wf[(col0 + 1) * 2 + 1];
    __shared__ float sm0[256], sm1[256];
    sm0[threadIdx.x] = p0; sm1[threadIdx.x] = p1; __syncthreads();
    for (int s = 128; s > 0; s >>= 1) {
        if (threadIdx.x < s) {
            sm0[threadIdx.x] += sm0[threadIdx.x + s];
            sm1[threadIdx.x] += sm1[threadIdx.x + s];
        }
        __syncthreads();
    }
    if (threadIdx.x == 0) {
        float l0 = sm0[0] + bf[0], l1 = sm1[0] + bf[1];
        l0 = (l0 >= 0.f) ? l0 : 0.01f * l0;
        l1 = (l1 >= 0.f) ? l1 : 0.01f * l1;
        float mx = fmaxf(l0, l1);
        float e0 = __expf(l0 - mx), e1 = __expf(l1 - mx);
        float inv = 1.0f / (e0 + e1);
        out[t * 2 + 0] = e0 * inv;
        out[t * 2 + 1] = e1 * inv;
    }
}

// -------------------------------- launch --------------------------------------
extern "C" void kernel_launch(void* const* d_in, const int* in_sizes, int n_in,
                              void* d_out, int out_size) {
    const int*   nf1   = (const int*)  d_in[0];
    const int*   nf2   = (const int*)  d_in[1];
    const float* emb1  = (const float*)d_in[2];
    const float* emb2  = (const float*)d_in[3];
    const float* Wiou1 = (const float*)d_in[4];
    const float* Wiou2 = (const float*)d_in[5];
    const float* Uiou1 = (const float*)d_in[6];
    const float* Uiou2 = (const float*)d_in[7];
    const float* UfW1  = (const float*)d_in[8];
    const float* Ufb1  = (const float*)d_in[9];
    const float* UfW2  = (const float*)d_in[10];
    const float* Ufb2  = (const float*)d_in[11];
    const float* biou1 = (const float*)d_in[12];
    const float* biou2 = (const float*)d_in[13];
    const float* Wf    = (const float*)d_in[14];
    const float* bf    = (const float*)d_in[15];
    float* out = (float*)d_out;

    float *iouS, *c, *cs;
    bf16 *Pb, *hb, *embB, *UfTb, *UiTb, *WiTb;
    cudaGetSymbolAddress((void**)&Pb,   g_Pb);
    cudaGetSymbolAddress((void**)&iouS, g_iou);
    cudaGetSymbolAddress((void**)&c,    g_c);
    cudaGetSymbolAddress((void**)&cs,   g_cs);
    cudaGetSymbolAddress((void**)&hb,   g_hb);
    cudaGetSymbolAddress((void**)&embB, g_embB);
    cudaGetSymbolAddress((void**)&UfTb, g_UfTb);
    cudaGetSymbolAddress((void**)&UiTb, g_UiTb);
    cudaGetSymbolAddress((void**)&WiTb, g_WiTb);

    const size_t Poff = (size_t)VOCAB * IOUW;
    const size_t Hoff = (size_t)NN * HID;
    const size_t Soff = (size_t)NINT * HID;
    const size_t Ioff = (size_t)NINT * IOUW;

    transpose_k<<<dim3(24, 8, 6), dim3(32, 8)>>>(
        TPair{UfW1, UfTb, 256},           TPair{UfW2, UfTb + 256*256, 256},
        TPair{Uiou1, UiTb, 768},          TPair{Uiou2, UiTb + 768*256, 768},
        TPair{Wiou1, WiTb, 768},          TPair{Wiou2, WiTb + 768*256, 768});
    conv_emb<<<(VOCAB*256 + 1023)/1024, 1024>>>(emb1, emb2);

    // P tables (bf16 out)
    {
        GemmArgs a0{embB,              WiTb,           nullptr, nullptr, Pb,        VOCAB, IOUW, 0, 1, 0, 2};
        GemmArgs a1{embB + VOCAB*256,  WiTb + 768*256, nullptr, nullptr, Pb + Poff, VOCAB, IOUW, 0, 1, 0, 2};
        mma_gemm<<<dim3(IOUW/128, (VOCAB + 127)/128, 2), 256>>>(a0, a1);
    }
    leaf_act_kernel<<<dim3(NLEAF, 1, 2), 128>>>(nf1, nf2, biou1, biou2);

    const int ps_[4]   = {21, 5, 1, 0};
    const int pcnt_[4] = {64, 16, 4, 1};
    const int cs_[4]   = {85, 21, 5, 1};
    const int ccnt_[4] = {256, 64, 16, 4};

    for (int L = 0; L < 4; L++) {
        int Mc = T_TREES * ccnt_[L];
        int Mp = T_TREES * pcnt_[L];
        int nf = 2 * ((Mc + 127) / 128);
        int nu = 6 * ((Mp + 127) / 128);
        GemmArgs f0{hb,        UfTb,           Ufb1, c,        cs,        Mc, 256, cs_[L], ccnt_[L], 1, 1};
        GemmArgs f1{hb + Hoff, UfTb + 256*256, Ufb2, c + Hoff, cs + Soff, Mc, 256, cs_[L], ccnt_[L], 1, 1};
        GemmArgs u0{hb,        UiTb,           nullptr, nullptr, iouS,        Mp, IOUW, cs_[L], pcnt_[L], 2, 0};
        GemmArgs u1{hb + Hoff, UiTb + 768*256, nullptr, nullptr, iouS + Ioff, Mp, IOUW, cs_[L], pcnt_[L], 2, 0};
        level_gemm<<<dim3(nf + nu, 1, 2), 256>>>(f0, f1, u0, u1, nf);
        act_kernel<<<dim3((Mp + 3)/4, 1, 2), 256>>>(biou1, biou2, Mp, ps_[L], pcnt_[L]);
    }

    readout_kernel<<<T_TREES, 256>>>(Wf, bf, out);
}